// round 4
// baseline (speedup 1.0000x reference)
#include <cuda_runtime.h>
#include <cuda_bf16.h>
#include <math.h>
#include <stdint.h>

// ---------------------------------------------------------------------------
// Problem constants (LlamaAttention: B=2,S=1024,P=1024,E=2048,H=32,KV=8,HD=64)
// ---------------------------------------------------------------------------
constexpr int B_   = 2;
constexpr int S_   = 1024;
constexpr int P_   = 1024;
constexpr int E_   = 2048;
constexpr int H_   = 32;
constexpr int KV_  = 8;
constexpr int HD_  = 64;
constexpr int G_   = H_ / KV_;        // 4
constexpr int CTX_ = P_ + S_;         // 2048
constexpr int M_   = B_ * S_;         // 2048 rows of tokens

// Scratch (static device allocations are the sanctioned workaround)
__device__ float g_Q[(size_t)M_ * E_];                       // fp32 Q (pre-rope)
__device__ float g_K[(size_t)M_ * KV_ * HD_];                // fp32 new K (pre-rope)
__device__ float g_V[(size_t)M_ * KV_ * HD_];                // fp32 new V
__device__ float g_O[(size_t)M_ * E_];                       // attention out fp32
__device__ uint2 g_Qhl[(size_t)M_ * H_ * 32];                // split Q (hi,lo bf16x2 pairs)
__device__ uint2 g_Khl[(size_t)B_ * KV_ * CTX_ * 32];        // split K  [b][kv][t][hd-pair]
__device__ uint2 g_Vthl[(size_t)B_ * KV_ * HD_ * (CTX_/2)];  // split V^T [b][kv][hd][t-pair]

// ---------------------------------------------------------------------------
// bf16x3 (Ootomo) helpers
// ---------------------------------------------------------------------------
__device__ __forceinline__ uint2 split2(float a, float b)
{
    __nv_bfloat162 h = __floats2bfloat162_rn(a, b);
    float ra = a - __low2float(h);
    float rb = b - __high2float(h);
    __nv_bfloat162 l = __floats2bfloat162_rn(ra, rb);
    uint2 r;
    r.x = *reinterpret_cast<uint32_t*>(&h);
    r.y = *reinterpret_cast<uint32_t*>(&l);
    return r;
}

__device__ __forceinline__ void mma_bf16(float c[4],
    uint32_t a0, uint32_t a1, uint32_t a2, uint32_t a3,
    uint32_t b0, uint32_t b1)
{
    asm volatile(
        "mma.sync.aligned.m16n8k16.row.col.f32.bf16.bf16.f32 "
        "{%0,%1,%2,%3}, {%4,%5,%6,%7}, {%8,%9}, {%0,%1,%2,%3};"
        : "+f"(c[0]), "+f"(c[1]), "+f"(c[2]), "+f"(c[3])
        : "r"(a0), "r"(a1), "r"(a2), "r"(a3), "r"(b0), "r"(b1));
}

// ---------------------------------------------------------------------------
// bf16x3 tensor-core GEMM core: C[m][n] = sum_k A[m][k] * W[n][k]
// 128x128 block, BK=32, 256 threads (8 warps as 2x4), warp tile 64x32.
// ---------------------------------------------------------------------------
constexpr int GSTR = 20;   // smem row stride in uint2 (16 pairs + pad 4)

struct SmemGemm {
    uint2 Ap[128 * GSTR];
    uint2 Bp[128 * GSTR];
};

__device__ __forceinline__ void gemm_core(
    const float* __restrict__ A, const float* __restrict__ W,
    float* __restrict__ C, int N, int K, int bm, int bn, SmemGemm* sm)
{
    constexpr int BK = 32;
    const int tid  = threadIdx.x;
    const int warp = tid >> 5;
    const int lane = tid & 31;
    const int g    = lane >> 2;        // 0..7
    const int tg   = lane & 3;         // 0..3
    const int wm   = (warp >> 2) * 64;
    const int wn   = (warp & 3) * 32;

    float acc[4][4][4];
#pragma unroll
    for (int i = 0; i < 4; i++)
#pragma unroll
        for (int j = 0; j < 4; j++)
#pragma unroll
            for (int r = 0; r < 4; r++) acc[i][j][r] = 0.f;

    const int lr = tid >> 1;            // 0..127
    const int pc = (tid & 1) * 8;       // pair offset 0 or 8
    const float* Ag = A + (size_t)(bm + lr) * K + pc * 2;
    const float* Wg = W + (size_t)(bn + lr) * K + pc * 2;
    uint2* AsW = &sm->Ap[lr * GSTR + pc];
    uint2* BsW = &sm->Bp[lr * GSTR + pc];

    for (int k0 = 0; k0 < K; k0 += BK) {
        float4 av[4], wv[4];
#pragma unroll
        for (int i = 0; i < 4; i++) {
            av[i] = *(const float4*)(Ag + k0 + i * 4);
            wv[i] = *(const float4*)(Wg + k0 + i * 4);
        }
        __syncthreads();
#pragma unroll
        for (int i = 0; i < 4; i++) {
            AsW[i * 2 + 0] = split2(av[i].x, av[i].y);
            AsW[i * 2 + 1] = split2(av[i].z, av[i].w);
            BsW[i * 2 + 0] = split2(wv[i].x, wv[i].y);
            BsW[i * 2 + 1] = split2(wv[i].z, wv[i].w);
        }
        __syncthreads();

#pragma unroll
        for (int ks = 0; ks < 2; ks++) {
            const int kp = ks * 8;
            uint2 ta[4][4];
#pragma unroll
            for (int mt = 0; mt < 4; mt++) {
                const int rb = wm + mt * 16;
                ta[mt][0] = sm->Ap[(rb + g)     * GSTR + kp + tg];
                ta[mt][1] = sm->Ap[(rb + g + 8) * GSTR + kp + tg];
                ta[mt][2] = sm->Ap[(rb + g)     * GSTR + kp + tg + 4];
                ta[mt][3] = sm->Ap[(rb + g + 8) * GSTR + kp + tg + 4];
            }
            uint2 tb[4][2];
#pragma unroll
            for (int nt = 0; nt < 4; nt++) {
                const int cb = wn + nt * 8;
                tb[nt][0] = sm->Bp[(cb + g) * GSTR + kp + tg];
                tb[nt][1] = sm->Bp[(cb + g) * GSTR + kp + tg + 4];
            }
#pragma unroll
            for (int mt = 0; mt < 4; mt++) {
#pragma unroll
                for (int nt = 0; nt < 4; nt++) {
                    mma_bf16(acc[mt][nt],
                             ta[mt][0].x, ta[mt][1].x, ta[mt][2].x, ta[mt][3].x,
                             tb[nt][0].y, tb[nt][1].y);
                    mma_bf16(acc[mt][nt],
                             ta[mt][0].y, ta[mt][1].y, ta[mt][2].y, ta[mt][3].y,
                             tb[nt][0].x, tb[nt][1].x);
                    mma_bf16(acc[mt][nt],
                             ta[mt][0].x, ta[mt][1].x, ta[mt][2].x, ta[mt][3].x,
                             tb[nt][0].x, tb[nt][1].x);
                }
            }
        }
    }

#pragma unroll
    for (int mt = 0; mt < 4; mt++) {
#pragma unroll
        for (int nt = 0; nt < 4; nt++) {
            const int row0 = bm + wm + mt * 16 + g;
            const int col  = bn + wn + nt * 8 + 2 * tg;
            *(float2*)&C[(size_t)row0 * N + col] =
                make_float2(acc[mt][nt][0], acc[mt][nt][1]);
            *(float2*)&C[(size_t)(row0 + 8) * N + col] =
                make_float2(acc[mt][nt][2], acc[mt][nt][3]);
        }
    }
}

// Fused Q+K+V projection: grid.x = 24 (16 Q, 4 K, 4 V).
__global__ __launch_bounds__(256) void sgemm_qkv(
    const float* __restrict__ x,
    const float* __restrict__ Wq, const float* __restrict__ Wk,
    const float* __restrict__ Wv)
{
    __shared__ SmemGemm sm;
    const int bx = blockIdx.x;
    if (bx < 16) {
        gemm_core(x, Wq, g_Q, E_, E_, blockIdx.y * 128, bx * 128, &sm);
    } else {
        const int c = bx - 16;
        const float* W = (c < 4) ? Wk : Wv;
        float* C       = (c < 4) ? g_K : g_V;
        gemm_core(x, W, C, KV_ * HD_, E_, blockIdx.y * 128, (c & 3) * 128, &sm);
    }
}

__global__ __launch_bounds__(256) void sgemm_bf16(
    const float* __restrict__ A, const float* __restrict__ W,
    float* __restrict__ C, int N, int K)
{
    __shared__ SmemGemm sm;
    gemm_core(A, W, C, N, K, blockIdx.y * 128, blockIdx.x * 128, &sm);
}

// ---------------------------------------------------------------------------
// RoPE + split: reads fp32 g_Q/g_K, writes split bf16 planes.
// One thread handles dims (2p,2p+1) and (2p+32,2p+33) of one (token,head).
// ---------------------------------------------------------------------------
__global__ void rope_split_kernel(const float* __restrict__ cosp,
                                  const float* __restrict__ sinp)
{
    int idx = blockIdx.x * blockDim.x + threadIdx.x;
    constexpr int NH = H_ + KV_;                 // 40
    if (idx >= M_ * NH * 16) return;
    const int p    = idx & 15;
    const int item = idx >> 4;
    const int hh   = item % NH;
    const int row  = item / NH;                  // b*S + s

    const float* cb = cosp + (size_t)row * HD_;
    const float* sb = sinp + (size_t)row * HD_;
    const float c1a = cb[2*p],      c1b = cb[2*p+1];
    const float s1a = sb[2*p],      s1b = sb[2*p+1];
    const float c2a = cb[2*p+32],   c2b = cb[2*p+33];
    const float s2a = sb[2*p+32],   s2b = sb[2*p+33];

    const float* base;
    uint2* dst;
    if (hh < H_) {
        base = g_Q + (size_t)row * E_ + hh * HD_;
        dst  = g_Qhl + ((size_t)row * H_ + hh) * 32;
    } else {
        const int kvh = hh - H_;
        base = g_K + (size_t)row * (KV_ * HD_) + kvh * HD_;
        const int b = row / S_, s = row % S_;
        dst  = g_Khl + ((size_t)(b * KV_ + kvh) * CTX_ + P_ + s) * 32;
    }
    const float t1a = base[2*p],    t1b = base[2*p+1];
    const float t2a = base[2*p+32], t2b = base[2*p+33];
    dst[p]      = split2(t1a * c1a - t2a * s1a, t1b * c1b - t2b * s1b);
    dst[p + 16] = split2(t2a * c2a + t1a * s2a, t2b * c2b + t1b * s2b);
}

// ---------------------------------------------------------------------------
// prep_kv: convert cached K (t<P) and all V (cache + new) into split planes.
// V is transposed to [hd][t-pair] via smem. Grid (CTX/64, KV, B), 256 thr.
// ---------------------------------------------------------------------------
__global__ __launch_bounds__(256) void prep_kv(
    const float* __restrict__ cache_k, const float* __restrict__ cache_v)
{
    __shared__ float Vs[64][68];
    const int t0 = blockIdx.x * 64;
    const int kv = blockIdx.y, b = blockIdx.z;
    const int tid = threadIdx.x;
    const int row = tid >> 2, q = tid & 3;       // row 0..63, q 0..3
    const int t = t0 + row;

    // K (cache region only; new K written by rope_split)
    if (t < P_) {
        const float* src = cache_k + ((size_t)(b * KV_ + kv) * CTX_ + t) * HD_ + q * 16;
        uint2* dst = g_Khl + ((size_t)(b * KV_ + kv) * CTX_ + t) * 32 + q * 8;
#pragma unroll
        for (int i = 0; i < 4; i++) {
            float4 f = ((const float4*)src)[i];
            dst[2 * i + 0] = split2(f.x, f.y);
            dst[2 * i + 1] = split2(f.z, f.w);
        }
    }

    // V: stage tile in smem
    const float* vsrc;
    if (t < P_)
        vsrc = cache_v + ((size_t)(b * KV_ + kv) * CTX_ + t) * HD_;
    else
        vsrc = g_V + (size_t)(b * S_ + (t - P_)) * (KV_ * HD_) + kv * HD_;
#pragma unroll
    for (int i = 0; i < 4; i++)
        *(float4*)&Vs[row][q * 16 + 4 * i] = ((const float4*)(vsrc + q * 16))[i];
    __syncthreads();

    // transpose write: thread -> (hd, 8 consecutive t-pairs)
    const int hd = tid >> 2, c = tid & 3;
    uint2* vdst = g_Vthl + ((size_t)(b * KV_ + kv) * HD_ + hd) * (CTX_ / 2)
                  + t0 / 2 + c * 8;
#pragma unroll
    for (int i = 0; i < 8; i++) {
        const int tp = c * 8 + i;
        vdst[i] = split2(Vs[2 * tp][hd], Vs[2 * tp + 1][hd]);
    }
}

// ---------------------------------------------------------------------------
// Flash attention on tensor cores (bf16x3, online softmax in registers).
// Grid (S/64, H, B), 128 threads = 4 warps x 16 rows.
// ---------------------------------------------------------------------------
__global__ __launch_bounds__(128) void attn_mma()
{
    __shared__ uint2 Ks[64 * 36];
    __shared__ uint2 Vts[64 * 36];

    const int m0 = blockIdx.x * 64;
    const int h  = blockIdx.y;
    const int b  = blockIdx.z;
    const int kv = h / G_;
    const int tid  = threadIdx.x;
    const int warp = tid >> 5;
    const int lane = tid & 31;
    const int g    = lane >> 2;
    const int tg   = lane & 3;

    // --- Q fragments (persist across all key tiles) ---
    uint32_t qhi[4][4], qlo[4][4];
    {
        const uint2* q0 = g_Qhl + ((size_t)(b * S_ + m0 + warp * 16 + g)     * H_ + h) * 32;
        const uint2* q8 = g_Qhl + ((size_t)(b * S_ + m0 + warp * 16 + g + 8) * H_ + h) * 32;
#pragma unroll
        for (int ks = 0; ks < 4; ks++) {
            uint2 u0 = q0[tg + 8 * ks];
            uint2 u1 = q8[tg + 8 * ks];
            uint2 u2 = q0[tg + 4 + 8 * ks];
            uint2 u3 = q8[tg + 4 + 8 * ks];
            qhi[ks][0] = u0.x; qhi[ks][1] = u1.x; qhi[ks][2] = u2.x; qhi[ks][3] = u3.x;
            qlo[ks][0] = u0.y; qlo[ks][1] = u1.y; qlo[ks][2] = u2.y; qlo[ks][3] = u3.y;
        }
    }

    float o[8][4];
#pragma unroll
    for (int nt = 0; nt < 8; nt++)
#pragma unroll
        for (int r = 0; r < 4; r++) o[nt][r] = 0.f;
    float m0s = -1e30f, m1s = -1e30f, l0 = 0.f, l1 = 0.f;

    const int qpos0 = P_ + m0 + warp * 16 + g;      // row g
    const int wmax  = P_ + m0 + warp * 16 + 15;     // warp's max qpos
    const int ntile = (P_ + m0 + 64) / 64;

    const uint2* kplane = g_Khl + (size_t)(b * KV_ + kv) * CTX_ * 32;
    const uint2* vplane = g_Vthl + (size_t)(b * KV_ + kv) * HD_ * (CTX_ / 2);

    const int lrow = tid >> 1, lh = tid & 1;

    for (int it = 0; it < ntile; ++it) {
        const int t0 = it * 64;
        __syncthreads();   // previous compute done with tiles
        {
            const uint4* ksrc = (const uint4*)(kplane + ((size_t)(t0 + lrow)) * 32) + lh * 8;
            uint4* kdst = (uint4*)&Ks[lrow * 36 + lh * 16];
#pragma unroll
            for (int i = 0; i < 8; i++) kdst[i] = ksrc[i];
            const uint4* vsrc = (const uint4*)(vplane + (size_t)lrow * (CTX_ / 2) + t0 / 2) + lh * 8;
            uint4* vdst = (uint4*)&Vts[lrow * 36 + lh * 16];
#pragma unroll
            for (int i = 0; i < 8; i++) vdst[i] = vsrc[i];
        }
        __syncthreads();

        if (t0 > wmax) continue;   // fully-masked for this warp (uniform)

        // --- scores S = Q K^T (bf16x3) ---
        float s[8][4];
#pragma unroll
        for (int nt = 0; nt < 8; nt++)
#pragma unroll
            for (int r = 0; r < 4; r++) s[nt][r] = 0.f;

#pragma unroll
        for (int nt = 0; nt < 8; nt++) {
            const uint2* kb = &Ks[(8 * nt + g) * 36 + tg];
#pragma unroll
            for (int ks = 0; ks < 4; ks++) {
                uint2 b0 = kb[8 * ks];
                uint2 b1 = kb[8 * ks + 4];
                mma_bf16(s[nt], qhi[ks][0], qhi[ks][1], qhi[ks][2], qhi[ks][3], b0.y, b1.y);
                mma_bf16(s[nt], qlo[ks][0], qlo[ks][1], qlo[ks][2], qlo[ks][3], b0.x, b1.x);
                mma_bf16(s[nt], qhi[ks][0], qhi[ks][1], qhi[ks][2], qhi[ks][3], b0.x, b1.x);
            }
        }

        // --- scale + causal mask ---
        const bool need_mask = (t0 + 63 > P_ + m0 + warp * 16);
        if (need_mask) {
#pragma unroll
            for (int nt = 0; nt < 8; nt++) {
                const int col = t0 + 8 * nt + 2 * tg;
#pragma unroll
                for (int r = 0; r < 4; r++) {
                    const int c  = col + (r & 1);
                    const int qp = (r < 2) ? qpos0 : qpos0 + 8;
                    s[nt][r] = (c > qp) ? -1e30f : s[nt][r] * 0.125f;
                }
            }
        } else {
#pragma unroll
            for (int nt = 0; nt < 8; nt++)
#pragma unroll
                for (int r = 0; r < 4; r++) s[nt][r] *= 0.125f;
        }

        // --- online softmax ---
        float mx0 = -1e30f, mx1 = -1e30f;
#pragma unroll
        for (int nt = 0; nt < 8; nt++) {
            mx0 = fmaxf(mx0, fmaxf(s[nt][0], s[nt][1]));
            mx1 = fmaxf(mx1, fmaxf(s[nt][2], s[nt][3]));
        }
        mx0 = fmaxf(mx0, __shfl_xor_sync(0xffffffffu, mx0, 1));
        mx0 = fmaxf(mx0, __shfl_xor_sync(0xffffffffu, mx0, 2));
        mx1 = fmaxf(mx1, __shfl_xor_sync(0xffffffffu, mx1, 1));
        mx1 = fmaxf(mx1, __shfl_xor_sync(0xffffffffu, mx1, 2));

        const float mn0 = fmaxf(m0s, mx0);
        const float mn1 = fmaxf(m1s, mx1);
        const float alpha0 = __expf(m0s - mn0);
        const float alpha1 = __expf(m1s - mn1);
        m0s = mn0; m1s = mn1;

        float sum0 = 0.f, sum1 = 0.f;
#pragma unroll
        for (int nt = 0; nt < 8; nt++) {
            s[nt][0] = __expf(s[nt][0] - mn0);
            s[nt][1] = __expf(s[nt][1] - mn0);
            s[nt][2] = __expf(s[nt][2] - mn1);
            s[nt][3] = __expf(s[nt][3] - mn1);
            sum0 += s[nt][0] + s[nt][1];
            sum1 += s[nt][2] + s[nt][3];
        }
        sum0 += __shfl_xor_sync(0xffffffffu, sum0, 1);
        sum0 += __shfl_xor_sync(0xffffffffu, sum0, 2);
        sum1 += __shfl_xor_sync(0xffffffffu, sum1, 1);
        sum1 += __shfl_xor_sync(0xffffffffu, sum1, 2);
        l0 = l0 * alpha0 + sum0;
        l1 = l1 * alpha1 + sum1;

#pragma unroll
        for (int nt = 0; nt < 8; nt++) {
            o[nt][0] *= alpha0; o[nt][1] *= alpha0;
            o[nt][2] *= alpha1; o[nt][3] *= alpha1;
        }

        // --- O += P V  (P straight from C-fragments, re-split) ---
#pragma unroll
        for (int ks = 0; ks < 4; ks++) {
            uint2 a0 = split2(s[2 * ks][0],     s[2 * ks][1]);
            uint2 a1 = split2(s[2 * ks][2],     s[2 * ks][3]);
            uint2 a2 = split2(s[2 * ks + 1][0], s[2 * ks + 1][1]);
            uint2 a3 = split2(s[2 * ks + 1][2], s[2 * ks + 1][3]);
            const uint2* vb = &Vts[g * 36 + tg + 8 * ks];
#pragma unroll
            for (int nt = 0; nt < 8; nt++) {
                uint2 b0 = vb[nt * 8 * 36];
                uint2 b1 = vb[nt * 8 * 36 + 4];
                mma_bf16(o[nt], a0.x, a1.x, a2.x, a3.x, b0.y, b1.y);
                mma_bf16(o[nt], a0.y, a1.y, a2.y, a3.y, b0.x, b1.x);
                mma_bf16(o[nt], a0.x, a1.x, a2.x, a3.x, b0.x, b1.x);
            }
        }
    }

    // --- epilogue ---
    const float inv0 = 1.f / l0;
    const float inv1 = 1.f / l1;
    float* d0 = g_O + (size_t)(b * S_ + m0 + warp * 16 + g)     * E_ + h * HD_ + 2 * tg;
    float* d8 = g_O + (size_t)(b * S_ + m0 + warp * 16 + g + 8) * E_ + h * HD_ + 2 * tg;
#pragma unroll
    for (int nt = 0; nt < 8; nt++) {
        *(float2*)(d0 + 8 * nt) = make_float2(o[nt][0] * inv0, o[nt][1] * inv0);
        *(float2*)(d8 + 8 * nt) = make_float2(o[nt][2] * inv1, o[nt][3] * inv1);
    }
}

// ---------------------------------------------------------------------------
// Launcher
// ---------------------------------------------------------------------------
extern "C" void kernel_launch(void* const* d_in, const int* in_sizes, int n_in,
                              void* d_out, int out_size)
{
    const float* x       = (const float*)d_in[0];
    const float* cosp    = (const float*)d_in[1];
    const float* sinp    = (const float*)d_in[2];
    // d_in[3] = mask (causal; computed analytically)
    const float* cache_k = (const float*)d_in[4];
    const float* cache_v = (const float*)d_in[5];
    const float* Wq      = (const float*)d_in[6];
    const float* Wk      = (const float*)d_in[7];
    const float* Wv      = (const float*)d_in[8];
    const float* Wo      = (const float*)d_in[9];
    float* out           = (float*)d_out;

    float* oP;
    cudaGetSymbolAddress((void**)&oP, g_O);

    // 1) fused Q/K/V projections (bf16x3 tensor cores)
    sgemm_qkv<<<dim3(24, M_ / 128), 256>>>(x, Wq, Wk, Wv);

    // 2) RoPE + bf16 split of Q and new K
    {
        const int total = M_ * (H_ + KV_) * 16;
        rope_split_kernel<<<(total + 255) / 256, 256>>>(cosp, sinp);
    }

    // 3) split cached K + all V (transposed)
    prep_kv<<<dim3(CTX_ / 64, KV_, B_), 256>>>(cache_k, cache_v);

    // 4) flash attention on tensor cores
    attn_mma<<<dim3(S_ / 64, H_, B_), 128>>>();

    // 5) output projection
    sgemm_bf16<<<dim3(E_ / 128, M_ / 128), 256>>>(oP, Wo, out, E_, E_);
}

// round 5
// speedup vs baseline: 1.4482x; 1.4482x over previous
#include <cuda_runtime.h>
#include <cuda_bf16.h>
#include <math.h>
#include <stdint.h>

// ---------------------------------------------------------------------------
// Problem constants (LlamaAttention: B=2,S=1024,P=1024,E=2048,H=32,KV=8,HD=64)
// ---------------------------------------------------------------------------
constexpr int B_   = 2;
constexpr int S_   = 1024;
constexpr int P_   = 1024;
constexpr int E_   = 2048;
constexpr int H_   = 32;
constexpr int KV_  = 8;
constexpr int HD_  = 64;
constexpr int G_   = H_ / KV_;        // 4
constexpr int CTX_ = P_ + S_;         // 2048
constexpr int M_   = B_ * S_;         // 2048 rows of tokens

// Scratch (static device allocations are the sanctioned workaround)
__device__ float g_Q[(size_t)M_ * E_];                       // fp32 Q (pre-rope)
__device__ float g_K[(size_t)M_ * KV_ * HD_];                // fp32 new K (pre-rope)
__device__ float g_V[(size_t)M_ * KV_ * HD_];                // fp32 new V
__device__ float g_O[(size_t)M_ * E_];                       // attention out fp32
__device__ uint2 g_Qhl[(size_t)M_ * H_ * 32];                // split Q (hi,lo bf16x2 pairs)
__device__ uint2 g_Khl[(size_t)B_ * KV_ * CTX_ * 32];        // split K  [b][kv][t][hd-pair]
__device__ uint2 g_Vthl[(size_t)B_ * KV_ * HD_ * (CTX_/2)];  // split V^T [b][kv][hd][t-pair]

// ---------------------------------------------------------------------------
// bf16x3 (Ootomo) helpers
// ---------------------------------------------------------------------------
__device__ __forceinline__ uint2 split2(float a, float b)
{
    __nv_bfloat162 h = __floats2bfloat162_rn(a, b);
    float ra = a - __low2float(h);
    float rb = b - __high2float(h);
    __nv_bfloat162 l = __floats2bfloat162_rn(ra, rb);
    uint2 r;
    r.x = *reinterpret_cast<uint32_t*>(&h);
    r.y = *reinterpret_cast<uint32_t*>(&l);
    return r;
}

__device__ __forceinline__ void mma_bf16(float c[4],
    uint32_t a0, uint32_t a1, uint32_t a2, uint32_t a3,
    uint32_t b0, uint32_t b1)
{
    asm volatile(
        "mma.sync.aligned.m16n8k16.row.col.f32.bf16.bf16.f32 "
        "{%0,%1,%2,%3}, {%4,%5,%6,%7}, {%8,%9}, {%0,%1,%2,%3};"
        : "+f"(c[0]), "+f"(c[1]), "+f"(c[2]), "+f"(c[3])
        : "r"(a0), "r"(a1), "r"(a2), "r"(a3), "r"(b0), "r"(b1));
}

__device__ __forceinline__ void cp16(void* smem_dst, const void* gsrc)
{
    uint32_t d = (uint32_t)__cvta_generic_to_shared(smem_dst);
    asm volatile("cp.async.cg.shared.global [%0], [%1], 16;" :: "r"(d), "l"(gsrc));
}

// ---------------------------------------------------------------------------
// bf16x3 tensor-core GEMM core: C[m][n] = sum_k A[m][k] * W[n][k]
// 128x128 block, BK=32, 256 threads (8 warps as 2x4), warp tile 64x32.
// Software-prefetched global loads (LDG issued before the mma burst).
// ---------------------------------------------------------------------------
constexpr int GSTR = 20;   // smem row stride in uint2 (16 pairs + pad 4)

struct SmemGemm {
    uint2 Ap[128 * GSTR];
    uint2 Bp[128 * GSTR];
};

__device__ __forceinline__ void gemm_core(
    const float* __restrict__ A, const float* __restrict__ W,
    float* __restrict__ C, int N, int K, int bm, int bn, SmemGemm* sm)
{
    constexpr int BK = 32;
    const int tid  = threadIdx.x;
    const int warp = tid >> 5;
    const int lane = tid & 31;
    const int g    = lane >> 2;        // 0..7
    const int tg   = lane & 3;         // 0..3
    const int wm   = (warp >> 2) * 64;
    const int wn   = (warp & 3) * 32;

    float acc[4][4][4];
#pragma unroll
    for (int i = 0; i < 4; i++)
#pragma unroll
        for (int j = 0; j < 4; j++)
#pragma unroll
            for (int r = 0; r < 4; r++) acc[i][j][r] = 0.f;

    const int lr = tid >> 1;            // 0..127
    const int pc = (tid & 1) * 8;       // pair offset 0 or 8
    const float* Ag = A + (size_t)(bm + lr) * K + pc * 2;
    const float* Wg = W + (size_t)(bn + lr) * K + pc * 2;
    uint2* AsW = &sm->Ap[lr * GSTR + pc];
    uint2* BsW = &sm->Bp[lr * GSTR + pc];

    float4 av[4], wv[4];
#pragma unroll
    for (int i = 0; i < 4; i++) {
        av[i] = *(const float4*)(Ag + i * 4);
        wv[i] = *(const float4*)(Wg + i * 4);
    }

    for (int k0 = 0; k0 < K; k0 += BK) {
        __syncthreads();
#pragma unroll
        for (int i = 0; i < 4; i++) {
            AsW[i * 2 + 0] = split2(av[i].x, av[i].y);
            AsW[i * 2 + 1] = split2(av[i].z, av[i].w);
            BsW[i * 2 + 0] = split2(wv[i].x, wv[i].y);
            BsW[i * 2 + 1] = split2(wv[i].z, wv[i].w);
        }
        __syncthreads();

        // prefetch next k-slice while mmas run
        if (k0 + BK < K) {
#pragma unroll
            for (int i = 0; i < 4; i++) {
                av[i] = *(const float4*)(Ag + k0 + BK + i * 4);
                wv[i] = *(const float4*)(Wg + k0 + BK + i * 4);
            }
        }

#pragma unroll
        for (int ks = 0; ks < 2; ks++) {
            const int kp = ks * 8;
            uint2 ta[4][4];
#pragma unroll
            for (int mt = 0; mt < 4; mt++) {
                const int rb = wm + mt * 16;
                ta[mt][0] = sm->Ap[(rb + g)     * GSTR + kp + tg];
                ta[mt][1] = sm->Ap[(rb + g + 8) * GSTR + kp + tg];
                ta[mt][2] = sm->Ap[(rb + g)     * GSTR + kp + tg + 4];
                ta[mt][3] = sm->Ap[(rb + g + 8) * GSTR + kp + tg + 4];
            }
            uint2 tb[4][2];
#pragma unroll
            for (int nt = 0; nt < 4; nt++) {
                const int cb = wn + nt * 8;
                tb[nt][0] = sm->Bp[(cb + g) * GSTR + kp + tg];
                tb[nt][1] = sm->Bp[(cb + g) * GSTR + kp + tg + 4];
            }
#pragma unroll
            for (int mt = 0; mt < 4; mt++) {
#pragma unroll
                for (int nt = 0; nt < 4; nt++) {
                    mma_bf16(acc[mt][nt],
                             ta[mt][0].x, ta[mt][1].x, ta[mt][2].x, ta[mt][3].x,
                             tb[nt][0].y, tb[nt][1].y);
                    mma_bf16(acc[mt][nt],
                             ta[mt][0].y, ta[mt][1].y, ta[mt][2].y, ta[mt][3].y,
                             tb[nt][0].x, tb[nt][1].x);
                    mma_bf16(acc[mt][nt],
                             ta[mt][0].x, ta[mt][1].x, ta[mt][2].x, ta[mt][3].x,
                             tb[nt][0].x, tb[nt][1].x);
                }
            }
        }
    }

#pragma unroll
    for (int mt = 0; mt < 4; mt++) {
#pragma unroll
        for (int nt = 0; nt < 4; nt++) {
            const int row0 = bm + wm + mt * 16 + g;
            const int col  = bn + wn + nt * 8 + 2 * tg;
            *(float2*)&C[(size_t)row0 * N + col] =
                make_float2(acc[mt][nt][0], acc[mt][nt][1]);
            *(float2*)&C[(size_t)(row0 + 8) * N + col] =
                make_float2(acc[mt][nt][2], acc[mt][nt][3]);
        }
    }
}

// Fused Q+K+V projection: grid.x = 24 (16 Q, 4 K, 4 V).
__global__ __launch_bounds__(256) void sgemm_qkv(
    const float* __restrict__ x,
    const float* __restrict__ Wq, const float* __restrict__ Wk,
    const float* __restrict__ Wv)
{
    __shared__ SmemGemm sm;
    const int bx = blockIdx.x;
    if (bx < 16) {
        gemm_core(x, Wq, g_Q, E_, E_, blockIdx.y * 128, bx * 128, &sm);
    } else {
        const int c = bx - 16;
        const float* W = (c < 4) ? Wk : Wv;
        float* C       = (c < 4) ? g_K : g_V;
        gemm_core(x, W, C, KV_ * HD_, E_, blockIdx.y * 128, (c & 3) * 128, &sm);
    }
}

__global__ __launch_bounds__(256) void sgemm_bf16(
    const float* __restrict__ A, const float* __restrict__ W,
    float* __restrict__ C, int N, int K)
{
    __shared__ SmemGemm sm;
    gemm_core(A, W, C, N, K, blockIdx.y * 128, blockIdx.x * 128, &sm);
}

// ---------------------------------------------------------------------------
// RoPE + split: reads fp32 g_Q/g_K, writes split bf16 planes.
// ---------------------------------------------------------------------------
__global__ void rope_split_kernel(const float* __restrict__ cosp,
                                  const float* __restrict__ sinp)
{
    int idx = blockIdx.x * blockDim.x + threadIdx.x;
    constexpr int NH = H_ + KV_;                 // 40
    if (idx >= M_ * NH * 16) return;
    const int p    = idx & 15;
    const int item = idx >> 4;
    const int hh   = item % NH;
    const int row  = item / NH;                  // b*S + s

    const float* cb = cosp + (size_t)row * HD_;
    const float* sb = sinp + (size_t)row * HD_;
    const float c1a = cb[2*p],      c1b = cb[2*p+1];
    const float s1a = sb[2*p],      s1b = sb[2*p+1];
    const float c2a = cb[2*p+32],   c2b = cb[2*p+33];
    const float s2a = sb[2*p+32],   s2b = sb[2*p+33];

    const float* base;
    uint2* dst;
    if (hh < H_) {
        base = g_Q + (size_t)row * E_ + hh * HD_;
        dst  = g_Qhl + ((size_t)row * H_ + hh) * 32;
    } else {
        const int kvh = hh - H_;
        base = g_K + (size_t)row * (KV_ * HD_) + kvh * HD_;
        const int b = row / S_, s = row % S_;
        dst  = g_Khl + ((size_t)(b * KV_ + kvh) * CTX_ + P_ + s) * 32;
    }
    const float t1a = base[2*p],    t1b = base[2*p+1];
    const float t2a = base[2*p+32], t2b = base[2*p+33];
    dst[p]      = split2(t1a * c1a - t2a * s1a, t1b * c1b - t2b * s1b);
    dst[p + 16] = split2(t2a * c2a + t1a * s2a, t2b * c2b + t1b * s2b);
}

// ---------------------------------------------------------------------------
// prep_kv: convert cached K (t<P) and all V (cache + new) into split planes.
// ---------------------------------------------------------------------------
__global__ __launch_bounds__(256) void prep_kv(
    const float* __restrict__ cache_k, const float* __restrict__ cache_v)
{
    __shared__ float Vs[64][68];
    const int t0 = blockIdx.x * 64;
    const int kv = blockIdx.y, b = blockIdx.z;
    const int tid = threadIdx.x;
    const int row = tid >> 2, q = tid & 3;
    const int t = t0 + row;

    if (t < P_) {
        const float* src = cache_k + ((size_t)(b * KV_ + kv) * CTX_ + t) * HD_ + q * 16;
        uint2* dst = g_Khl + ((size_t)(b * KV_ + kv) * CTX_ + t) * 32 + q * 8;
#pragma unroll
        for (int i = 0; i < 4; i++) {
            float4 f = ((const float4*)src)[i];
            dst[2 * i + 0] = split2(f.x, f.y);
            dst[2 * i + 1] = split2(f.z, f.w);
        }
    }

    const float* vsrc;
    if (t < P_)
        vsrc = cache_v + ((size_t)(b * KV_ + kv) * CTX_ + t) * HD_;
    else
        vsrc = g_V + (size_t)(b * S_ + (t - P_)) * (KV_ * HD_) + kv * HD_;
#pragma unroll
    for (int i = 0; i < 4; i++)
        *(float4*)&Vs[row][q * 16 + 4 * i] = ((const float4*)(vsrc + q * 16))[i];
    __syncthreads();

    const int hd = tid >> 2, c = tid & 3;
    uint2* vdst = g_Vthl + ((size_t)(b * KV_ + kv) * HD_ + hd) * (CTX_ / 2)
                  + t0 / 2 + c * 8;
#pragma unroll
    for (int i = 0; i < 8; i++) {
        const int tp = c * 8 + i;
        vdst[i] = split2(Vs[2 * tp][hd], Vs[2 * tp + 1][hd]);
    }
}

// ---------------------------------------------------------------------------
// Flash attention on tensor cores, double-buffered cp.async pipeline.
// Grid (S/64, H, B), 128 threads = 4 warps x 16 rows.
// ---------------------------------------------------------------------------
constexpr int ATTN_TILE_U2 = 64 * 36;                 // uint2 per K or V tile
constexpr int ATTN_SMEM    = 2 * 2 * ATTN_TILE_U2 * 8; // 73728 B

__global__ __launch_bounds__(128) void attn_mma()
{
    extern __shared__ uint2 smbuf[];
    uint2* KsB[2]  = { smbuf,                    smbuf + ATTN_TILE_U2 };
    uint2* VtsB[2] = { smbuf + 2 * ATTN_TILE_U2, smbuf + 3 * ATTN_TILE_U2 };

    const int m0 = blockIdx.x * 64;
    const int h  = blockIdx.y;
    const int b  = blockIdx.z;
    const int kv = h / G_;
    const int tid  = threadIdx.x;
    const int warp = tid >> 5;
    const int lane = tid & 31;
    const int g    = lane >> 2;
    const int tg   = lane & 3;

    const uint2* kplane = g_Khl + (size_t)(b * KV_ + kv) * CTX_ * 32;
    const uint2* vplane = g_Vthl + (size_t)(b * KV_ + kv) * HD_ * (CTX_ / 2);
    const int lrow = tid >> 1, lh = tid & 1;
    const int ntile = (P_ + m0 + 64) / 64;

    // kick off tile 0 loads
    {
        const uint2* ksrc = kplane + (size_t)lrow * 32 + lh * 16;
        uint2* kdst = KsB[0] + lrow * 36 + lh * 16;
        const uint2* vsrc = vplane + (size_t)lrow * (CTX_ / 2) + lh * 16;
        uint2* vdst = VtsB[0] + lrow * 36 + lh * 16;
#pragma unroll
        for (int i = 0; i < 8; i++) { cp16(kdst + 2 * i, ksrc + 2 * i); }
#pragma unroll
        for (int i = 0; i < 8; i++) { cp16(vdst + 2 * i, vsrc + 2 * i); }
        asm volatile("cp.async.commit_group;");
    }

    // --- Q fragments (persist across all key tiles) ---
    uint32_t qhi[4][4], qlo[4][4];
    {
        const uint2* q0 = g_Qhl + ((size_t)(b * S_ + m0 + warp * 16 + g)     * H_ + h) * 32;
        const uint2* q8 = g_Qhl + ((size_t)(b * S_ + m0 + warp * 16 + g + 8) * H_ + h) * 32;
#pragma unroll
        for (int ks = 0; ks < 4; ks++) {
            uint2 u0 = q0[tg + 8 * ks];
            uint2 u1 = q8[tg + 8 * ks];
            uint2 u2 = q0[tg + 4 + 8 * ks];
            uint2 u3 = q8[tg + 4 + 8 * ks];
            qhi[ks][0] = u0.x; qhi[ks][1] = u1.x; qhi[ks][2] = u2.x; qhi[ks][3] = u3.x;
            qlo[ks][0] = u0.y; qlo[ks][1] = u1.y; qlo[ks][2] = u2.y; qlo[ks][3] = u3.y;
        }
    }

    float o[8][4];
#pragma unroll
    for (int nt = 0; nt < 8; nt++)
#pragma unroll
        for (int r = 0; r < 4; r++) o[nt][r] = 0.f;
    float m0s = -1e30f, m1s = -1e30f, l0 = 0.f, l1 = 0.f;

    const int qpos0 = P_ + m0 + warp * 16 + g;
    const int wmax  = P_ + m0 + warp * 16 + 15;

    for (int it = 0; it < ntile; ++it) {
        const int t0 = it * 64;
        const int buf = it & 1;

        // prefetch tile it+1 into the other buffer
        if (it + 1 < ntile) {
            const int nb = (it + 1) & 1;
            const uint2* ksrc = kplane + (size_t)(t0 + 64 + lrow) * 32 + lh * 16;
            uint2* kdst = KsB[nb] + lrow * 36 + lh * 16;
            const uint2* vsrc = vplane + (size_t)lrow * (CTX_ / 2) + (t0 + 64) / 2 + lh * 16;
            uint2* vdst = VtsB[nb] + lrow * 36 + lh * 16;
#pragma unroll
            for (int i = 0; i < 8; i++) { cp16(kdst + 2 * i, ksrc + 2 * i); }
#pragma unroll
            for (int i = 0; i < 8; i++) { cp16(vdst + 2 * i, vsrc + 2 * i); }
            asm volatile("cp.async.commit_group;");
            asm volatile("cp.async.wait_group 1;");
        } else {
            asm volatile("cp.async.wait_group 0;");
        }
        __syncthreads();    // tile `it` visible to all warps

        if (t0 <= wmax) {
            const uint2* KsC  = KsB[buf];
            const uint2* VtsC = VtsB[buf];

            // --- scores S = Q K^T (bf16x3), ks-outer for 8-way ILP ---
            float s[8][4];
#pragma unroll
            for (int nt = 0; nt < 8; nt++)
#pragma unroll
                for (int r = 0; r < 4; r++) s[nt][r] = 0.f;

#pragma unroll
            for (int ks = 0; ks < 4; ks++) {
#pragma unroll
                for (int nt = 0; nt < 8; nt++) {
                    const uint2* kb = &KsC[(8 * nt + g) * 36 + tg + 8 * ks];
                    uint2 b0 = kb[0];
                    uint2 b1 = kb[4];
                    mma_bf16(s[nt], qhi[ks][0], qhi[ks][1], qhi[ks][2], qhi[ks][3], b0.y, b1.y);
                    mma_bf16(s[nt], qlo[ks][0], qlo[ks][1], qlo[ks][2], qlo[ks][3], b0.x, b1.x);
                    mma_bf16(s[nt], qhi[ks][0], qhi[ks][1], qhi[ks][2], qhi[ks][3], b0.x, b1.x);
                }
            }

            // --- scale + causal mask ---
            const bool need_mask = (t0 + 63 > P_ + m0 + warp * 16);
            if (need_mask) {
#pragma unroll
                for (int nt = 0; nt < 8; nt++) {
                    const int col = t0 + 8 * nt + 2 * tg;
#pragma unroll
                    for (int r = 0; r < 4; r++) {
                        const int c  = col + (r & 1);
                        const int qp = (r < 2) ? qpos0 : qpos0 + 8;
                        s[nt][r] = (c > qp) ? -1e30f : s[nt][r] * 0.125f;
                    }
                }
            } else {
#pragma unroll
                for (int nt = 0; nt < 8; nt++)
#pragma unroll
                    for (int r = 0; r < 4; r++) s[nt][r] *= 0.125f;
            }

            // --- online softmax ---
            float mx0 = -1e30f, mx1 = -1e30f;
#pragma unroll
            for (int nt = 0; nt < 8; nt++) {
                mx0 = fmaxf(mx0, fmaxf(s[nt][0], s[nt][1]));
                mx1 = fmaxf(mx1, fmaxf(s[nt][2], s[nt][3]));
            }
            mx0 = fmaxf(mx0, __shfl_xor_sync(0xffffffffu, mx0, 1));
            mx0 = fmaxf(mx0, __shfl_xor_sync(0xffffffffu, mx0, 2));
            mx1 = fmaxf(mx1, __shfl_xor_sync(0xffffffffu, mx1, 1));
            mx1 = fmaxf(mx1, __shfl_xor_sync(0xffffffffu, mx1, 2));

            const float mn0 = fmaxf(m0s, mx0);
            const float mn1 = fmaxf(m1s, mx1);
            const float alpha0 = __expf(m0s - mn0);
            const float alpha1 = __expf(m1s - mn1);
            m0s = mn0; m1s = mn1;

            float sum0 = 0.f, sum1 = 0.f;
#pragma unroll
            for (int nt = 0; nt < 8; nt++) {
                s[nt][0] = __expf(s[nt][0] - mn0);
                s[nt][1] = __expf(s[nt][1] - mn0);
                s[nt][2] = __expf(s[nt][2] - mn1);
                s[nt][3] = __expf(s[nt][3] - mn1);
                sum0 += s[nt][0] + s[nt][1];
                sum1 += s[nt][2] + s[nt][3];
            }
            sum0 += __shfl_xor_sync(0xffffffffu, sum0, 1);
            sum0 += __shfl_xor_sync(0xffffffffu, sum0, 2);
            sum1 += __shfl_xor_sync(0xffffffffu, sum1, 1);
            sum1 += __shfl_xor_sync(0xffffffffu, sum1, 2);
            l0 = l0 * alpha0 + sum0;
            l1 = l1 * alpha1 + sum1;

#pragma unroll
            for (int nt = 0; nt < 8; nt++) {
                o[nt][0] *= alpha0; o[nt][1] *= alpha0;
                o[nt][2] *= alpha1; o[nt][3] *= alpha1;
            }

            // --- O += P V  (P straight from C-fragments, re-split) ---
#pragma unroll
            for (int ks = 0; ks < 4; ks++) {
                uint2 a0 = split2(s[2 * ks][0],     s[2 * ks][1]);
                uint2 a1 = split2(s[2 * ks][2],     s[2 * ks][3]);
                uint2 a2 = split2(s[2 * ks + 1][0], s[2 * ks + 1][1]);
                uint2 a3 = split2(s[2 * ks + 1][2], s[2 * ks + 1][3]);
                const uint2* vb = &VtsC[g * 36 + tg + 8 * ks];
#pragma unroll
                for (int nt = 0; nt < 8; nt++) {
                    uint2 b0 = vb[nt * 8 * 36];
                    uint2 b1 = vb[nt * 8 * 36 + 4];
                    mma_bf16(o[nt], a0.x, a1.x, a2.x, a3.x, b0.y, b1.y);
                    mma_bf16(o[nt], a0.y, a1.y, a2.y, a3.y, b0.x, b1.x);
                    mma_bf16(o[nt], a0.x, a1.x, a2.x, a3.x, b0.x, b1.x);
                }
            }
        }

        __syncthreads();    // everyone done with buf before it is overwritten
    }

    // --- epilogue ---
    const float inv0 = 1.f / l0;
    const float inv1 = 1.f / l1;
    float* d0 = g_O + (size_t)(b * S_ + m0 + warp * 16 + g)     * E_ + h * HD_ + 2 * tg;
    float* d8 = g_O + (size_t)(b * S_ + m0 + warp * 16 + g + 8) * E_ + h * HD_ + 2 * tg;
#pragma unroll
    for (int nt = 0; nt < 8; nt++) {
        *(float2*)(d0 + 8 * nt) = make_float2(o[nt][0] * inv0, o[nt][1] * inv0);
        *(float2*)(d8 + 8 * nt) = make_float2(o[nt][2] * inv1, o[nt][3] * inv1);
    }
}

// ---------------------------------------------------------------------------
// Launcher
// ---------------------------------------------------------------------------
extern "C" void kernel_launch(void* const* d_in, const int* in_sizes, int n_in,
                              void* d_out, int out_size)
{
    const float* x       = (const float*)d_in[0];
    const float* cosp    = (const float*)d_in[1];
    const float* sinp    = (const float*)d_in[2];
    // d_in[3] = mask (causal; computed analytically)
    const float* cache_k = (const float*)d_in[4];
    const float* cache_v = (const float*)d_in[5];
    const float* Wq      = (const float*)d_in[6];
    const float* Wk      = (const float*)d_in[7];
    const float* Wv      = (const float*)d_in[8];
    const float* Wo      = (const float*)d_in[9];
    float* out           = (float*)d_out;

    float* oP;
    cudaGetSymbolAddress((void**)&oP, g_O);

    cudaFuncSetAttribute(attn_mma,
                         cudaFuncAttributeMaxDynamicSharedMemorySize, ATTN_SMEM);

    // 1) fused Q/K/V projections (bf16x3 tensor cores)
    sgemm_qkv<<<dim3(24, M_ / 128), 256>>>(x, Wq, Wk, Wv);

    // 2) RoPE + bf16 split of Q and new K
    {
        const int total = M_ * (H_ + KV_) * 16;
        rope_split_kernel<<<(total + 255) / 256, 256>>>(cosp, sinp);
    }

    // 3) split cached K + all V (transposed)
    prep_kv<<<dim3(CTX_ / 64, KV_, B_), 256>>>(cache_k, cache_v);

    // 4) flash attention on tensor cores (double-buffered)
    attn_mma<<<dim3(S_ / 64, H_, B_), 128, ATTN_SMEM>>>();

    // 5) output projection
    sgemm_bf16<<<dim3(E_ / 128, M_ / 128), 256>>>(oP, Wo, out, E_, E_);
}

// round 7
// speedup vs baseline: 2.6340x; 1.8188x over previous
#include <cuda_runtime.h>
#include <cuda_fp16.h>
#include <math.h>
#include <stdint.h>

// ---------------------------------------------------------------------------
// Problem constants (LlamaAttention: B=2,S=1024,P=1024,E=2048,H=32,KV=8,HD=64)
// ---------------------------------------------------------------------------
constexpr int B_   = 2;
constexpr int S_   = 1024;
constexpr int P_   = 1024;
constexpr int E_   = 2048;
constexpr int H_   = 32;
constexpr int KV_  = 8;
constexpr int HD_  = 64;
constexpr int G_   = H_ / KV_;        // 4
constexpr int CTX_ = P_ + S_;         // 2048
constexpr int M_   = B_ * S_;         // 2048 rows of tokens

// ---------------------------------------------------------------------------
// Scratch (static device allocations are the sanctioned workaround)
// ---------------------------------------------------------------------------
__device__ float    g_Q[(size_t)M_ * E_];                   // fp32 Q (pre-rope)
__device__ float    g_K[(size_t)M_ * KV_ * HD_];            // fp32 new K (pre-rope)
__device__ float    g_V[(size_t)M_ * KV_ * HD_];            // fp32 new V
__device__ uint2    g_Xp[(size_t)M_ * E_ / 2];              // x as fp16 (hi,lo) pairs
__device__ uint2    g_Ap[(size_t)M_ * E_ / 2];              // attn out fp16 pairs
__device__ uint32_t g_Wq16[(size_t)E_ * E_ / 2];            // fp16 packed weights
__device__ uint32_t g_Wk16[(size_t)KV_ * HD_ * E_ / 2];
__device__ uint32_t g_Wv16[(size_t)KV_ * HD_ * E_ / 2];
__device__ uint32_t g_Wo16[(size_t)E_ * E_ / 2];
__device__ uint2    g_Qhl[(size_t)M_ * H_ * 32];            // split Q fp16 pairs
__device__ uint32_t g_K16[(size_t)B_ * KV_ * CTX_ * 32];    // K fp16 [b][kv][t][hd/2]
__device__ uint32_t g_Vt16[(size_t)B_ * KV_ * HD_ * (CTX_/2)]; // V^T fp16 [b][kv][hd][t/2]

// ---------------------------------------------------------------------------
// fp16 split helpers
// ---------------------------------------------------------------------------
__device__ __forceinline__ uint2 split2h(float a, float b)
{
    __half2 h = __floats2half2_rn(a, b);
    float ra = a - __low2float(h);
    float rb = b - __high2float(h);
    __half2 l = __floats2half2_rn(ra, rb);
    uint2 r;
    r.x = *reinterpret_cast<uint32_t*>(&h);
    r.y = *reinterpret_cast<uint32_t*>(&l);
    return r;
}

__device__ __forceinline__ uint32_t h2pack(float a, float b)
{
    __half2 h = __floats2half2_rn(a, b);
    return *reinterpret_cast<uint32_t*>(&h);
}

__device__ __forceinline__ void mma_f16(float c[4],
    uint32_t a0, uint32_t a1, uint32_t a2, uint32_t a3,
    uint32_t b0, uint32_t b1)
{
    asm volatile(
        "mma.sync.aligned.m16n8k16.row.col.f32.f16.f16.f32 "
        "{%0,%1,%2,%3}, {%4,%5,%6,%7}, {%8,%9}, {%0,%1,%2,%3};"
        : "+f"(c[0]), "+f"(c[1]), "+f"(c[2]), "+f"(c[3])
        : "r"(a0), "r"(a1), "r"(a2), "r"(a3), "r"(b0), "r"(b1));
}

__device__ __forceinline__ void cp16(void* smem_dst, const void* gsrc)
{
    uint32_t d = (uint32_t)__cvta_generic_to_shared(smem_dst);
    asm volatile("cp.async.cg.shared.global [%0], [%1], 16;" :: "r"(d), "l"(gsrc));
}

// ---------------------------------------------------------------------------
// prep: fp32 -> fp16 pair / single planes
// ---------------------------------------------------------------------------
__global__ void split_pairs(const float* __restrict__ src, uint2* __restrict__ dst, int npair)
{
    int i = blockIdx.x * blockDim.x + threadIdx.x;
    if (i >= npair) return;
    float2 f = *(const float2*)(src + 2 * i);
    dst[i] = split2h(f.x, f.y);
}

__global__ void tohalf_pairs(const float* __restrict__ src, uint32_t* __restrict__ dst, int npair)
{
    int i = blockIdx.x * blockDim.x + threadIdx.x;
    if (i >= npair) return;
    float2 f = *(const float2*)(src + 2 * i);
    dst[i] = h2pack(f.x, f.y);
}

// ---------------------------------------------------------------------------
// fp16x2 GEMM:  C[m][n] = sum_k A[m][k] * W[n][k]
// A: fp16 (hi,lo) pairs; W: single fp16. 128x128 tile, BK=32, 256 threads,
// 8 warps (2x4), warp tile 64x32, double-buffered cp.async staging.
// ---------------------------------------------------------------------------
constexpr int GSTR2 = 20;             // A stride in uint2 / B stride in uint32 (16 used + 4 pad)
constexpr int A_ST  = 128 * GSTR2;    // uint2 per A stage
constexpr int B_ST  = 128 * GSTR2;    // uint32 per B stage
constexpr int GSM2  = 2 * A_ST * 8 + 2 * B_ST * 4;   // 61440 B

__device__ __forceinline__ void gemm2_stage(
    const uint2* __restrict__ Ap, const uint32_t* __restrict__ Bh,
    int Kp, int bm, int bn, int kp0, uint2* Ad, uint32_t* Bd, int tid)
{
#pragma unroll
    for (int i = 0; i < 4; i++) {
        int c = tid * 4 + i;
        int row = c >> 3, off = c & 7;
        cp16(Ad + row * GSTR2 + off * 2,
             Ap + (size_t)(bm + row) * Kp + kp0 + off * 2);
    }
#pragma unroll
    for (int i = 0; i < 2; i++) {
        int c = tid * 2 + i;
        int row = c >> 2, off = c & 3;
        cp16(Bd + row * GSTR2 + off * 4,
             Bh + (size_t)(bn + row) * Kp + kp0 + off * 4);
    }
    asm volatile("cp.async.commit_group;" ::: "memory");
}

__device__ __forceinline__ void gemm2_core(
    const uint2* __restrict__ Ap, const uint32_t* __restrict__ Bh,
    float* __restrict__ C, int N, int K, int bm, int bn, char* smraw)
{
    uint2*    As = (uint2*)smraw;
    uint32_t* Bs = (uint32_t*)(smraw + 2 * A_ST * 8);
    const int tid  = threadIdx.x;
    const int warp = tid >> 5;
    const int lane = tid & 31;
    const int g    = lane >> 2;
    const int tg   = lane & 3;
    const int wm   = (warp >> 2) * 64;
    const int wn   = (warp & 3) * 32;
    const int Kp   = K / 2;

    float acc[4][4][4];
#pragma unroll
    for (int i = 0; i < 4; i++)
#pragma unroll
        for (int j = 0; j < 4; j++)
#pragma unroll
            for (int r = 0; r < 4; r++) acc[i][j][r] = 0.f;

    const int nst = K / 32;
    gemm2_stage(Ap, Bh, Kp, bm, bn, 0,  As,        Bs,        tid);
    gemm2_stage(Ap, Bh, Kp, bm, bn, 16, As + A_ST, Bs + B_ST, tid);

    for (int s = 0; s < nst; s++) {
        const int buf = s & 1;
        if (s < nst - 1)
            asm volatile("cp.async.wait_group 1;" ::: "memory");
        else
            asm volatile("cp.async.wait_group 0;" ::: "memory");
        __syncthreads();

        const uint2*    Ab = As + buf * A_ST;
        const uint32_t* Bb = Bs + buf * B_ST;

#pragma unroll
        for (int ks = 0; ks < 2; ks++) {
            const int kp = ks * 8;
            uint2 ta[4][4];
#pragma unroll
            for (int mt = 0; mt < 4; mt++) {
                const int rb = wm + mt * 16;
                ta[mt][0] = Ab[(rb + g)     * GSTR2 + kp + tg];
                ta[mt][1] = Ab[(rb + g + 8) * GSTR2 + kp + tg];
                ta[mt][2] = Ab[(rb + g)     * GSTR2 + kp + tg + 4];
                ta[mt][3] = Ab[(rb + g + 8) * GSTR2 + kp + tg + 4];
            }
            uint32_t tb[4][2];
#pragma unroll
            for (int nt = 0; nt < 4; nt++) {
                const int cb = wn + nt * 8;
                tb[nt][0] = Bb[(cb + g) * GSTR2 + kp + tg];
                tb[nt][1] = Bb[(cb + g) * GSTR2 + kp + tg + 4];
            }
#pragma unroll
            for (int mt = 0; mt < 4; mt++) {
#pragma unroll
                for (int nt = 0; nt < 4; nt++) {
                    mma_f16(acc[mt][nt],
                            ta[mt][0].x, ta[mt][1].x, ta[mt][2].x, ta[mt][3].x,
                            tb[nt][0], tb[nt][1]);
                    mma_f16(acc[mt][nt],
                            ta[mt][0].y, ta[mt][1].y, ta[mt][2].y, ta[mt][3].y,
                            tb[nt][0], tb[nt][1]);
                }
            }
        }
        __syncthreads();
        if (s + 2 < nst)
            gemm2_stage(Ap, Bh, Kp, bm, bn, (s + 2) * 16,
                        As + buf * A_ST, Bs + buf * B_ST, tid);
    }

    // epilogue
#pragma unroll
    for (int mt = 0; mt < 4; mt++) {
#pragma unroll
        for (int nt = 0; nt < 4; nt++) {
            const int row0 = bm + wm + mt * 16 + g;
            const int col  = bn + wn + nt * 8 + 2 * tg;
            *(float2*)&C[(size_t)row0 * N + col] =
                make_float2(acc[mt][nt][0], acc[mt][nt][1]);
            *(float2*)&C[(size_t)(row0 + 8) * N + col] =
                make_float2(acc[mt][nt][2], acc[mt][nt][3]);
        }
    }
}

// Fused Q+K+V projection: grid (24, 16). bx<16: Q; 16-19: K; 20-23: V.
__global__ __launch_bounds__(256, 2) void gemm_qkv()
{
    extern __shared__ char smraw[];
    const int bx = blockIdx.x, bm = blockIdx.y * 128;
    if (bx < 16)
        gemm2_core(g_Xp, g_Wq16, g_Q, E_, E_, bm, bx * 128, smraw);
    else if (bx < 20)
        gemm2_core(g_Xp, g_Wk16, g_K, KV_ * HD_, E_, bm, (bx - 16) * 128, smraw);
    else
        gemm2_core(g_Xp, g_Wv16, g_V, KV_ * HD_, E_, bm, (bx - 20) * 128, smraw);
}

__global__ __launch_bounds__(256, 2) void gemm_o(float* __restrict__ out)
{
    extern __shared__ char smraw[];
    gemm2_core(g_Ap, g_Wo16, out, E_, E_, blockIdx.y * 128, blockIdx.x * 128, smraw);
}

// ---------------------------------------------------------------------------
// RoPE + fp16 split: Q -> pairs, new K -> single plane.
// ---------------------------------------------------------------------------
__global__ void rope_split_kernel(const float* __restrict__ cosp,
                                  const float* __restrict__ sinp)
{
    int idx = blockIdx.x * blockDim.x + threadIdx.x;
    constexpr int NH = H_ + KV_;                 // 40
    if (idx >= M_ * NH * 16) return;
    const int p    = idx & 15;
    const int item = idx >> 4;
    const int hh   = item % NH;
    const int row  = item / NH;                  // b*S + s

    const float* cb = cosp + (size_t)row * HD_;
    const float* sb = sinp + (size_t)row * HD_;
    const float c1a = cb[2*p],      c1b = cb[2*p+1];
    const float s1a = sb[2*p],      s1b = sb[2*p+1];
    const float c2a = cb[2*p+32],   c2b = cb[2*p+33];
    const float s2a = sb[2*p+32],   s2b = sb[2*p+33];

    if (hh < H_) {
        const float* base = g_Q + (size_t)row * E_ + hh * HD_;
        uint2* dst = g_Qhl + ((size_t)row * H_ + hh) * 32;
        const float t1a = base[2*p],    t1b = base[2*p+1];
        const float t2a = base[2*p+32], t2b = base[2*p+33];
        dst[p]      = split2h(t1a * c1a - t2a * s1a, t1b * c1b - t2b * s1b);
        dst[p + 16] = split2h(t2a * c2a + t1a * s2a, t2b * c2b + t1b * s2b);
    } else {
        const int kvh = hh - H_;
        const float* base = g_K + (size_t)row * (KV_ * HD_) + kvh * HD_;
        const int b = row / S_, s = row % S_;
        uint32_t* dst = g_K16 + ((size_t)(b * KV_ + kvh) * CTX_ + P_ + s) * 32;
        const float t1a = base[2*p],    t1b = base[2*p+1];
        const float t2a = base[2*p+32], t2b = base[2*p+33];
        dst[p]      = h2pack(t1a * c1a - t2a * s1a, t1b * c1b - t2b * s1b);
        dst[p + 16] = h2pack(t2a * c2a + t1a * s2a, t2b * c2b + t1b * s2b);
    }
}

// ---------------------------------------------------------------------------
// prep_kv: cached K -> fp16 plane; all V -> fp16 transposed plane.
// ---------------------------------------------------------------------------
__global__ __launch_bounds__(256) void prep_kv(
    const float* __restrict__ cache_k, const float* __restrict__ cache_v)
{
    __shared__ float Vs[64][68];
    const int t0 = blockIdx.x * 64;
    const int kv = blockIdx.y, b = blockIdx.z;
    const int tid = threadIdx.x;
    const int row = tid >> 2, q = tid & 3;
    const int t = t0 + row;

    if (t < P_) {
        const float* src = cache_k + ((size_t)(b * KV_ + kv) * CTX_ + t) * HD_ + q * 16;
        uint32_t* dst = g_K16 + ((size_t)(b * KV_ + kv) * CTX_ + t) * 32 + q * 8;
#pragma unroll
        for (int i = 0; i < 4; i++) {
            float4 f = ((const float4*)src)[i];
            dst[2 * i + 0] = h2pack(f.x, f.y);
            dst[2 * i + 1] = h2pack(f.z, f.w);
        }
    }

    const float* vsrc;
    if (t < P_)
        vsrc = cache_v + ((size_t)(b * KV_ + kv) * CTX_ + t) * HD_;
    else
        vsrc = g_V + (size_t)(b * S_ + (t - P_)) * (KV_ * HD_) + kv * HD_;
#pragma unroll
    for (int i = 0; i < 4; i++)
        *(float4*)&Vs[row][q * 16 + 4 * i] = ((const float4*)(vsrc + q * 16))[i];
    __syncthreads();

    const int hd = tid >> 2, c = tid & 3;
    uint32_t* vdst = g_Vt16 + ((size_t)(b * KV_ + kv) * HD_ + hd) * (CTX_ / 2)
                   + t0 / 2 + c * 8;
#pragma unroll
    for (int i = 0; i < 8; i++) {
        const int tp = c * 8 + i;
        vdst[i] = h2pack(Vs[2 * tp][hd], Vs[2 * tp + 1][hd]);
    }
}

// ---------------------------------------------------------------------------
// Flash attention (fp16x2), double-buffered cp.async pipeline.
// Grid (S/64, H, B), 128 threads = 4 warps x 16 rows.
// ---------------------------------------------------------------------------
constexpr int KT = 64 * 36;   // uint32 per K or V tile (stride 36, 32 used)

__global__ __launch_bounds__(128) void attn_mma()
{
    __shared__ uint32_t KsS[2][KT];
    __shared__ uint32_t VtS[2][KT];

    const int m0 = blockIdx.x * 64;
    const int h  = blockIdx.y;
    const int b  = blockIdx.z;
    const int kv = h / G_;
    const int tid  = threadIdx.x;
    const int warp = tid >> 5;
    const int lane = tid & 31;
    const int g    = lane >> 2;
    const int tg   = lane & 3;

    const uint32_t* kplane = g_K16 + (size_t)(b * KV_ + kv) * CTX_ * 32;
    const uint32_t* vplane = g_Vt16 + (size_t)(b * KV_ + kv) * HD_ * (CTX_ / 2);
    const int lrow = tid >> 1, lh = tid & 1;
    const int ntile = (P_ + m0 + 64) / 64;

    // kick off tile 0 loads
    {
        const uint32_t* ksrc = kplane + (size_t)lrow * 32 + lh * 16;
        uint32_t* kdst = &KsS[0][lrow * 36 + lh * 16];
        const uint32_t* vsrc = vplane + (size_t)lrow * (CTX_ / 2) + lh * 16;
        uint32_t* vdst = &VtS[0][lrow * 36 + lh * 16];
#pragma unroll
        for (int i = 0; i < 4; i++) { cp16(kdst + 4 * i, ksrc + 4 * i); }
#pragma unroll
        for (int i = 0; i < 4; i++) { cp16(vdst + 4 * i, vsrc + 4 * i); }
        asm volatile("cp.async.commit_group;");
    }

    // Q fragments (fp16 hi/lo pairs), persist across tiles
    uint32_t qhi[4][4], qlo[4][4];
    {
        const uint2* q0 = g_Qhl + ((size_t)(b * S_ + m0 + warp * 16 + g)     * H_ + h) * 32;
        const uint2* q8 = g_Qhl + ((size_t)(b * S_ + m0 + warp * 16 + g + 8) * H_ + h) * 32;
#pragma unroll
        for (int ks = 0; ks < 4; ks++) {
            uint2 u0 = q0[tg + 8 * ks];
            uint2 u1 = q8[tg + 8 * ks];
            uint2 u2 = q0[tg + 4 + 8 * ks];
            uint2 u3 = q8[tg + 4 + 8 * ks];
            qhi[ks][0] = u0.x; qhi[ks][1] = u1.x; qhi[ks][2] = u2.x; qhi[ks][3] = u3.x;
            qlo[ks][0] = u0.y; qlo[ks][1] = u1.y; qlo[ks][2] = u2.y; qlo[ks][3] = u3.y;
        }
    }

    float o[8][4];
#pragma unroll
    for (int nt = 0; nt < 8; nt++)
#pragma unroll
        for (int r = 0; r < 4; r++) o[nt][r] = 0.f;
    float m0s = -1e30f, m1s = -1e30f, l0 = 0.f, l1 = 0.f;

    const int qpos0 = P_ + m0 + warp * 16 + g;
    const int wmax  = P_ + m0 + warp * 16 + 15;

    for (int it = 0; it < ntile; ++it) {
        const int t0 = it * 64;
        const int buf = it & 1;

        if (it + 1 < ntile) {
            const int nb = (it + 1) & 1;
            const uint32_t* ksrc = kplane + (size_t)(t0 + 64 + lrow) * 32 + lh * 16;
            uint32_t* kdst = &KsS[nb][lrow * 36 + lh * 16];
            const uint32_t* vsrc = vplane + (size_t)lrow * (CTX_ / 2) + (t0 + 64) / 2 + lh * 16;
            uint32_t* vdst = &VtS[nb][lrow * 36 + lh * 16];
#pragma unroll
            for (int i = 0; i < 4; i++) { cp16(kdst + 4 * i, ksrc + 4 * i); }
#pragma unroll
            for (int i = 0; i < 4; i++) { cp16(vdst + 4 * i, vsrc + 4 * i); }
            asm volatile("cp.async.commit_group;");
            asm volatile("cp.async.wait_group 1;");
        } else {
            asm volatile("cp.async.wait_group 0;");
        }
        __syncthreads();

        if (t0 <= wmax) {
            const uint32_t* KsC = KsS[buf];
            const uint32_t* VtC = VtS[buf];

            // --- scores S = Q K^T (fp16x2): 2 mmas per (ks, nt) ---
            float s[8][4];
#pragma unroll
            for (int nt = 0; nt < 8; nt++)
#pragma unroll
                for (int r = 0; r < 4; r++) s[nt][r] = 0.f;

#pragma unroll
            for (int ks = 0; ks < 4; ks++) {
#pragma unroll
                for (int nt = 0; nt < 8; nt++) {
                    const uint32_t* kb = &KsC[(8 * nt + g) * 36 + 8 * ks + tg];
                    uint32_t b0 = kb[0];
                    uint32_t b1 = kb[4];
                    mma_f16(s[nt], qhi[ks][0], qhi[ks][1], qhi[ks][2], qhi[ks][3], b0, b1);
                    mma_f16(s[nt], qlo[ks][0], qlo[ks][1], qlo[ks][2], qlo[ks][3], b0, b1);
                }
            }

            // --- scale + causal mask ---
            const bool need_mask = (t0 + 63 > P_ + m0 + warp * 16);
            if (need_mask) {
#pragma unroll
                for (int nt = 0; nt < 8; nt++) {
                    const int col = t0 + 8 * nt + 2 * tg;
#pragma unroll
                    for (int r = 0; r < 4; r++) {
                        const int c  = col + (r & 1);
                        const int qp = (r < 2) ? qpos0 : qpos0 + 8;
                        s[nt][r] = (c > qp) ? -1e30f : s[nt][r] * 0.125f;
                    }
                }
            } else {
#pragma unroll
                for (int nt = 0; nt < 8; nt++)
#pragma unroll
                    for (int r = 0; r < 4; r++) s[nt][r] *= 0.125f;
            }

            // --- online softmax ---
            float mx0 = -1e30f, mx1 = -1e30f;
#pragma unroll
            for (int nt = 0; nt < 8; nt++) {
                mx0 = fmaxf(mx0, fmaxf(s[nt][0], s[nt][1]));
                mx1 = fmaxf(mx1, fmaxf(s[nt][2], s[nt][3]));
            }
            mx0 = fmaxf(mx0, __shfl_xor_sync(0xffffffffu, mx0, 1));
            mx0 = fmaxf(mx0, __shfl_xor_sync(0xffffffffu, mx0, 2));
            mx1 = fmaxf(mx1, __shfl_xor_sync(0xffffffffu, mx1, 1));
            mx1 = fmaxf(mx1, __shfl_xor_sync(0xffffffffu, mx1, 2));

            const float mn0 = fmaxf(m0s, mx0);
            const float mn1 = fmaxf(m1s, mx1);
            const float alpha0 = __expf(m0s - mn0);
            const float alpha1 = __expf(m1s - mn1);
            m0s = mn0; m1s = mn1;

            float sum0 = 0.f, sum1 = 0.f;
#pragma unroll
            for (int nt = 0; nt < 8; nt++) {
                s[nt][0] = __expf(s[nt][0] - mn0);
                s[nt][1] = __expf(s[nt][1] - mn0);
                s[nt][2] = __expf(s[nt][2] - mn1);
                s[nt][3] = __expf(s[nt][3] - mn1);
                sum0 += s[nt][0] + s[nt][1];
                sum1 += s[nt][2] + s[nt][3];
            }
            sum0 += __shfl_xor_sync(0xffffffffu, sum0, 1);
            sum0 += __shfl_xor_sync(0xffffffffu, sum0, 2);
            sum1 += __shfl_xor_sync(0xffffffffu, sum1, 1);
            sum1 += __shfl_xor_sync(0xffffffffu, sum1, 2);
            l0 = l0 * alpha0 + sum0;
            l1 = l1 * alpha1 + sum1;

#pragma unroll
            for (int nt = 0; nt < 8; nt++) {
                o[nt][0] *= alpha0; o[nt][1] *= alpha0;
                o[nt][2] *= alpha1; o[nt][3] *= alpha1;
            }

            // --- O += P V (P split fp16x2 from C-fragments, V single fp16) ---
#pragma unroll
            for (int ks = 0; ks < 4; ks++) {
                uint2 a0 = split2h(s[2 * ks][0],     s[2 * ks][1]);
                uint2 a1 = split2h(s[2 * ks][2],     s[2 * ks][3]);
                uint2 a2 = split2h(s[2 * ks + 1][0], s[2 * ks + 1][1]);
                uint2 a3 = split2h(s[2 * ks + 1][2], s[2 * ks + 1][3]);
#pragma unroll
                for (int nt = 0; nt < 8; nt++) {
                    const uint32_t* vb = &VtC[(8 * nt + g) * 36 + 8 * ks + tg];
                    uint32_t b0 = vb[0];
                    uint32_t b1 = vb[4];
                    mma_f16(o[nt], a0.x, a1.x, a2.x, a3.x, b0, b1);
                    mma_f16(o[nt], a0.y, a1.y, a2.y, a3.y, b0, b1);
                }
            }
        }

        __syncthreads();
    }

    // --- epilogue: write fp16 pairs for the O projection ---
    const float inv0 = 1.f / l0;
    const float inv1 = 1.f / l1;
    const size_t row0  = (size_t)(b * S_ + m0 + warp * 16 + g);
    const size_t base0 = row0 * (E_ / 2) + h * (HD_ / 2) + tg;
    const size_t base8 = base0 + 4 * E_;     // +8 rows (8 * E/2)
#pragma unroll
    for (int nt = 0; nt < 8; nt++) {
        g_Ap[base0 + 4 * nt] = split2h(o[nt][0] * inv0, o[nt][1] * inv0);
        g_Ap[base8 + 4 * nt] = split2h(o[nt][2] * inv1, o[nt][3] * inv1);
    }
}

// ---------------------------------------------------------------------------
// Launcher
// ---------------------------------------------------------------------------
extern "C" void kernel_launch(void* const* d_in, const int* in_sizes, int n_in,
                              void* d_out, int out_size)
{
    const float* x       = (const float*)d_in[0];
    const float* cosp    = (const float*)d_in[1];
    const float* sinp    = (const float*)d_in[2];
    // d_in[3] = mask (causal; computed analytically)
    const float* cache_k = (const float*)d_in[4];
    const float* cache_v = (const float*)d_in[5];
    const float* Wq      = (const float*)d_in[6];
    const float* Wk      = (const float*)d_in[7];
    const float* Wv      = (const float*)d_in[8];
    const float* Wo      = (const float*)d_in[9];
    float* out           = (float*)d_out;

    uint2* xp;
    uint32_t *wq16, *wk16, *wv16, *wo16;
    cudaGetSymbolAddress((void**)&xp,   g_Xp);
    cudaGetSymbolAddress((void**)&wq16, g_Wq16);
    cudaGetSymbolAddress((void**)&wk16, g_Wk16);
    cudaGetSymbolAddress((void**)&wv16, g_Wv16);
    cudaGetSymbolAddress((void**)&wo16, g_Wo16);

    cudaFuncSetAttribute(gemm_qkv, cudaFuncAttributeMaxDynamicSharedMemorySize, GSM2);
    cudaFuncSetAttribute(gemm_o,   cudaFuncAttributeMaxDynamicSharedMemorySize, GSM2);

    // 0) fp16 planes: x -> (hi,lo) pairs; weights -> single fp16
    split_pairs<<<(M_ * E_ / 2 + 255) / 256, 256>>>(x, xp, M_ * E_ / 2);
    tohalf_pairs<<<(E_ * E_ / 2 + 255) / 256, 256>>>(Wq, wq16, E_ * E_ / 2);
    tohalf_pairs<<<(KV_ * HD_ * E_ / 2 + 255) / 256, 256>>>(Wk, wk16, KV_ * HD_ * E_ / 2);
    tohalf_pairs<<<(KV_ * HD_ * E_ / 2 + 255) / 256, 256>>>(Wv, wv16, KV_ * HD_ * E_ / 2);
    tohalf_pairs<<<(E_ * E_ / 2 + 255) / 256, 256>>>(Wo, wo16, E_ * E_ / 2);

    // 1) fused Q/K/V projections (fp16x2 tensor cores)
    gemm_qkv<<<dim3(24, M_ / 128), 256, GSM2>>>();

    // 2) RoPE + fp16 split of Q and new K
    {
        const int total = M_ * (H_ + KV_) * 16;
        rope_split_kernel<<<(total + 255) / 256, 256>>>(cosp, sinp);
    }

    // 3) cached K + all V into fp16 planes (V transposed)
    prep_kv<<<dim3(CTX_ / 64, KV_, B_), 256>>>(cache_k, cache_v);

    // 4) flash attention (fp16x2, double-buffered)
    attn_mma<<<dim3(S_ / 64, H_, B_), 128>>>();

    // 5) output projection (fp16x2)
    gemm_o<<<dim3(16, 16), 256, GSM2>>>(out);
}

// round 8
// speedup vs baseline: 2.8800x; 1.0934x over previous
#include <cuda_runtime.h>
#include <cuda_fp16.h>
#include <math.h>
#include <stdint.h>

// ---------------------------------------------------------------------------
// Problem constants (LlamaAttention: B=2,S=1024,P=1024,E=2048,H=32,KV=8,HD=64)
// ---------------------------------------------------------------------------
constexpr int B_   = 2;
constexpr int S_   = 1024;
constexpr int P_   = 1024;
constexpr int E_   = 2048;
constexpr int H_   = 32;
constexpr int KV_  = 8;
constexpr int HD_  = 64;
constexpr int G_   = H_ / KV_;        // 4
constexpr int CTX_ = P_ + S_;         // 2048
constexpr int M_   = B_ * S_;         // 2048 rows of tokens

// ---------------------------------------------------------------------------
// Scratch (static device allocations are the sanctioned workaround)
// ---------------------------------------------------------------------------
__device__ float    g_Q[(size_t)M_ * E_];                   // fp32 Q (pre-rope)
__device__ float    g_K[(size_t)M_ * KV_ * HD_];            // fp32 new K (pre-rope)
__device__ float    g_V[(size_t)M_ * KV_ * HD_];            // fp32 new V
__device__ uint2    g_Xp[(size_t)M_ * E_ / 2];              // x as fp16 (hi,lo) pairs
__device__ uint2    g_Ap[(size_t)M_ * E_ / 2];              // attn out fp16 pairs
__device__ uint32_t g_Wq16[(size_t)E_ * E_ / 2];            // fp16 packed weights
__device__ uint32_t g_Wk16[(size_t)KV_ * HD_ * E_ / 2];
__device__ uint32_t g_Wv16[(size_t)KV_ * HD_ * E_ / 2];
__device__ uint32_t g_Wo16[(size_t)E_ * E_ / 2];
__device__ uint2    g_Qhl[(size_t)M_ * H_ * 32];            // split Q fp16 pairs
__device__ uint32_t g_K16[(size_t)B_ * KV_ * CTX_ * 32];    // K fp16 [b][kv][t][hd/2]
__device__ uint32_t g_Vt16[(size_t)B_ * KV_ * HD_ * (CTX_/2)]; // V^T fp16 [b][kv][hd][t/2]

// ---------------------------------------------------------------------------
// fp16 split helpers
// ---------------------------------------------------------------------------
__device__ __forceinline__ uint2 split2h(float a, float b)
{
    __half2 h = __floats2half2_rn(a, b);
    float ra = a - __low2float(h);
    float rb = b - __high2float(h);
    __half2 l = __floats2half2_rn(ra, rb);
    uint2 r;
    r.x = *reinterpret_cast<uint32_t*>(&h);
    r.y = *reinterpret_cast<uint32_t*>(&l);
    return r;
}

__device__ __forceinline__ uint32_t h2pack(float a, float b)
{
    __half2 h = __floats2half2_rn(a, b);
    return *reinterpret_cast<uint32_t*>(&h);
}

__device__ __forceinline__ void mma_f16(float c[4],
    uint32_t a0, uint32_t a1, uint32_t a2, uint32_t a3,
    uint32_t b0, uint32_t b1)
{
    asm volatile(
        "mma.sync.aligned.m16n8k16.row.col.f32.f16.f16.f32 "
        "{%0,%1,%2,%3}, {%4,%5,%6,%7}, {%8,%9}, {%0,%1,%2,%3};"
        : "+f"(c[0]), "+f"(c[1]), "+f"(c[2]), "+f"(c[3])
        : "r"(a0), "r"(a1), "r"(a2), "r"(a3), "r"(b0), "r"(b1));
}

__device__ __forceinline__ void cp16(void* smem_dst, const void* gsrc)
{
    uint32_t d = (uint32_t)__cvta_generic_to_shared(smem_dst);
    asm volatile("cp.async.cg.shared.global [%0], [%1], 16;" :: "r"(d), "l"(gsrc));
}

// ---------------------------------------------------------------------------
// prep: fp32 -> fp16 pair / single planes
// ---------------------------------------------------------------------------
__global__ void split_pairs(const float* __restrict__ src, uint2* __restrict__ dst, int npair)
{
    int i = blockIdx.x * blockDim.x + threadIdx.x;
    if (i >= npair) return;
    float2 f = *(const float2*)(src + 2 * i);
    dst[i] = split2h(f.x, f.y);
}

__global__ void tohalf_pairs(const float* __restrict__ src, uint32_t* __restrict__ dst, int npair)
{
    int i = blockIdx.x * blockDim.x + threadIdx.x;
    if (i >= npair) return;
    float2 f = *(const float2*)(src + 2 * i);
    dst[i] = h2pack(f.x, f.y);
}

// ---------------------------------------------------------------------------
// fp16x2 GEMM:  C[m][n] = sum_k A[m][k] * W[n][k]
// A: fp16 (hi,lo) pairs; W: single fp16. 128x128 tile, BK=32, 256 threads,
// 8 warps (2x4), warp tile 64x32, double-buffered cp.async staging.
// ---------------------------------------------------------------------------
constexpr int GSTR2 = 20;             // A stride in uint2 / B stride in uint32 (16 used + 4 pad)
constexpr int A_ST  = 128 * GSTR2;    // uint2 per A stage
constexpr int B_ST  = 128 * GSTR2;    // uint32 per B stage
constexpr int GSM2  = 2 * A_ST * 8 + 2 * B_ST * 4;   // 61440 B

__device__ __forceinline__ void gemm2_stage(
    const uint2* __restrict__ Ap, const uint32_t* __restrict__ Bh,
    int Kp, int bm, int bn, int kp0, uint2* Ad, uint32_t* Bd, int tid)
{
#pragma unroll
    for (int i = 0; i < 4; i++) {
        int c = tid * 4 + i;
        int row = c >> 3, off = c & 7;
        cp16(Ad + row * GSTR2 + off * 2,
             Ap + (size_t)(bm + row) * Kp + kp0 + off * 2);
    }
#pragma unroll
    for (int i = 0; i < 2; i++) {
        int c = tid * 2 + i;
        int row = c >> 2, off = c & 3;
        cp16(Bd + row * GSTR2 + off * 4,
             Bh + (size_t)(bn + row) * Kp + kp0 + off * 4);
    }
    asm volatile("cp.async.commit_group;" ::: "memory");
}

__device__ __forceinline__ void gemm2_core(
    const uint2* __restrict__ Ap, const uint32_t* __restrict__ Bh,
    float* __restrict__ C, int N, int K, int bm, int bn, char* smraw)
{
    uint2*    As = (uint2*)smraw;
    uint32_t* Bs = (uint32_t*)(smraw + 2 * A_ST * 8);
    const int tid  = threadIdx.x;
    const int warp = tid >> 5;
    const int lane = tid & 31;
    const int g    = lane >> 2;
    const int tg   = lane & 3;
    const int wm   = (warp >> 2) * 64;
    const int wn   = (warp & 3) * 32;
    const int Kp   = K / 2;

    float acc[4][4][4];
#pragma unroll
    for (int i = 0; i < 4; i++)
#pragma unroll
        for (int j = 0; j < 4; j++)
#pragma unroll
            for (int r = 0; r < 4; r++) acc[i][j][r] = 0.f;

    const int nst = K / 32;
    gemm2_stage(Ap, Bh, Kp, bm, bn, 0,  As,        Bs,        tid);
    gemm2_stage(Ap, Bh, Kp, bm, bn, 16, As + A_ST, Bs + B_ST, tid);

    for (int s = 0; s < nst; s++) {
        const int buf = s & 1;
        if (s < nst - 1)
            asm volatile("cp.async.wait_group 1;" ::: "memory");
        else
            asm volatile("cp.async.wait_group 0;" ::: "memory");
        __syncthreads();

        const uint2*    Ab = As + buf * A_ST;
        const uint32_t* Bb = Bs + buf * B_ST;

#pragma unroll
        for (int ks = 0; ks < 2; ks++) {
            const int kp = ks * 8;
            uint2 ta[4][4];
#pragma unroll
            for (int mt = 0; mt < 4; mt++) {
                const int rb = wm + mt * 16;
                ta[mt][0] = Ab[(rb + g)     * GSTR2 + kp + tg];
                ta[mt][1] = Ab[(rb + g + 8) * GSTR2 + kp + tg];
                ta[mt][2] = Ab[(rb + g)     * GSTR2 + kp + tg + 4];
                ta[mt][3] = Ab[(rb + g + 8) * GSTR2 + kp + tg + 4];
            }
            uint32_t tb[4][2];
#pragma unroll
            for (int nt = 0; nt < 4; nt++) {
                const int cb = wn + nt * 8;
                tb[nt][0] = Bb[(cb + g) * GSTR2 + kp + tg];
                tb[nt][1] = Bb[(cb + g) * GSTR2 + kp + tg + 4];
            }
#pragma unroll
            for (int mt = 0; mt < 4; mt++) {
#pragma unroll
                for (int nt = 0; nt < 4; nt++) {
                    mma_f16(acc[mt][nt],
                            ta[mt][0].x, ta[mt][1].x, ta[mt][2].x, ta[mt][3].x,
                            tb[nt][0], tb[nt][1]);
                    mma_f16(acc[mt][nt],
                            ta[mt][0].y, ta[mt][1].y, ta[mt][2].y, ta[mt][3].y,
                            tb[nt][0], tb[nt][1]);
                }
            }
        }
        __syncthreads();
        if (s + 2 < nst)
            gemm2_stage(Ap, Bh, Kp, bm, bn, (s + 2) * 16,
                        As + buf * A_ST, Bs + buf * B_ST, tid);
    }

    // epilogue
#pragma unroll
    for (int mt = 0; mt < 4; mt++) {
#pragma unroll
        for (int nt = 0; nt < 4; nt++) {
            const int row0 = bm + wm + mt * 16 + g;
            const int col  = bn + wn + nt * 8 + 2 * tg;
            *(float2*)&C[(size_t)row0 * N + col] =
                make_float2(acc[mt][nt][0], acc[mt][nt][1]);
            *(float2*)&C[(size_t)(row0 + 8) * N + col] =
                make_float2(acc[mt][nt][2], acc[mt][nt][3]);
        }
    }
}

// Fused Q+K+V projection: grid (24, 16). bx<16: Q; 16-19: K; 20-23: V.
__global__ __launch_bounds__(256, 2) void gemm_qkv()
{
    extern __shared__ char smraw[];
    const int bx = blockIdx.x, bm = blockIdx.y * 128;
    if (bx < 16)
        gemm2_core(g_Xp, g_Wq16, g_Q, E_, E_, bm, bx * 128, smraw);
    else if (bx < 20)
        gemm2_core(g_Xp, g_Wk16, g_K, KV_ * HD_, E_, bm, (bx - 16) * 128, smraw);
    else
        gemm2_core(g_Xp, g_Wv16, g_V, KV_ * HD_, E_, bm, (bx - 20) * 128, smraw);
}

__global__ __launch_bounds__(256, 2) void gemm_o(float* __restrict__ out)
{
    extern __shared__ char smraw[];
    gemm2_core(g_Ap, g_Wo16, out, E_, E_, blockIdx.y * 128, blockIdx.x * 128, smraw);
}

// ---------------------------------------------------------------------------
// RoPE + fp16 split: Q -> pairs, new K -> single plane.
// ---------------------------------------------------------------------------
__global__ void rope_split_kernel(const float* __restrict__ cosp,
                                  const float* __restrict__ sinp)
{
    int idx = blockIdx.x * blockDim.x + threadIdx.x;
    constexpr int NH = H_ + KV_;                 // 40
    if (idx >= M_ * NH * 16) return;
    const int p    = idx & 15;
    const int item = idx >> 4;
    const int hh   = item % NH;
    const int row  = item / NH;                  // b*S + s

    const float* cb = cosp + (size_t)row * HD_;
    const float* sb = sinp + (size_t)row * HD_;
    const float c1a = cb[2*p],      c1b = cb[2*p+1];
    const float s1a = sb[2*p],      s1b = sb[2*p+1];
    const float c2a = cb[2*p+32],   c2b = cb[2*p+33];
    const float s2a = sb[2*p+32],   s2b = sb[2*p+33];

    if (hh < H_) {
        const float* base = g_Q + (size_t)row * E_ + hh * HD_;
        uint2* dst = g_Qhl + ((size_t)row * H_ + hh) * 32;
        const float t1a = base[2*p],    t1b = base[2*p+1];
        const float t2a = base[2*p+32], t2b = base[2*p+33];
        dst[p]      = split2h(t1a * c1a - t2a * s1a, t1b * c1b - t2b * s1b);
        dst[p + 16] = split2h(t2a * c2a + t1a * s2a, t2b * c2b + t1b * s2b);
    } else {
        const int kvh = hh - H_;
        const float* base = g_K + (size_t)row * (KV_ * HD_) + kvh * HD_;
        const int b = row / S_, s = row % S_;
        uint32_t* dst = g_K16 + ((size_t)(b * KV_ + kvh) * CTX_ + P_ + s) * 32;
        const float t1a = base[2*p],    t1b = base[2*p+1];
        const float t2a = base[2*p+32], t2b = base[2*p+33];
        dst[p]      = h2pack(t1a * c1a - t2a * s1a, t1b * c1b - t2b * s1b);
        dst[p + 16] = h2pack(t2a * c2a + t1a * s2a, t2b * c2b + t1b * s2b);
    }
}

// ---------------------------------------------------------------------------
// prep_kv: cached K -> fp16 plane; all V -> fp16 transposed plane.
// ---------------------------------------------------------------------------
__global__ __launch_bounds__(256) void prep_kv(
    const float* __restrict__ cache_k, const float* __restrict__ cache_v)
{
    __shared__ float Vs[64][68];
    const int t0 = blockIdx.x * 64;
    const int kv = blockIdx.y, b = blockIdx.z;
    const int tid = threadIdx.x;
    const int row = tid >> 2, q = tid & 3;
    const int t = t0 + row;

    if (t < P_) {
        const float* src = cache_k + ((size_t)(b * KV_ + kv) * CTX_ + t) * HD_ + q * 16;
        uint32_t* dst = g_K16 + ((size_t)(b * KV_ + kv) * CTX_ + t) * 32 + q * 8;
#pragma unroll
        for (int i = 0; i < 4; i++) {
            float4 f = ((const float4*)src)[i];
            dst[2 * i + 0] = h2pack(f.x, f.y);
            dst[2 * i + 1] = h2pack(f.z, f.w);
        }
    }

    const float* vsrc;
    if (t < P_)
        vsrc = cache_v + ((size_t)(b * KV_ + kv) * CTX_ + t) * HD_;
    else
        vsrc = g_V + (size_t)(b * S_ + (t - P_)) * (KV_ * HD_) + kv * HD_;
#pragma unroll
    for (int i = 0; i < 4; i++)
        *(float4*)&Vs[row][q * 16 + 4 * i] = ((const float4*)(vsrc + q * 16))[i];
    __syncthreads();

    const int hd = tid >> 2, c = tid & 3;
    uint32_t* vdst = g_Vt16 + ((size_t)(b * KV_ + kv) * HD_ + hd) * (CTX_ / 2)
                   + t0 / 2 + c * 8;
#pragma unroll
    for (int i = 0; i < 8; i++) {
        const int tp = c * 8 + i;
        vdst[i] = h2pack(Vs[2 * tp][hd], Vs[2 * tp + 1][hd]);
    }
}

// ---------------------------------------------------------------------------
// Flash attention (fp16x2 scores, fp16x1 PV), BLOCK_M=128, 8 warps.
// Grid (S/128, H, B), 256 threads; double-buffered cp.async K/V tiles.
// ---------------------------------------------------------------------------
constexpr int KT = 64 * 36;   // uint32 per K or V tile (stride 36, 32 used)

__global__ __launch_bounds__(256, 2) void attn_mma()
{
    __shared__ uint32_t KsS[2][KT];
    __shared__ uint32_t VtS[2][KT];

    // longest blocks (largest m0) first
    const int mblk = (int)gridDim.x - 1 - (int)blockIdx.x;
    const int m0 = mblk * 128;
    const int h  = blockIdx.y;
    const int b  = blockIdx.z;
    const int kv = h / G_;
    const int tid  = threadIdx.x;
    const int warp = tid >> 5;
    const int lane = tid & 31;
    const int g    = lane >> 2;
    const int tg   = lane & 3;

    const uint32_t* kplane = g_K16 + (size_t)(b * KV_ + kv) * CTX_ * 32;
    const uint32_t* vplane = g_Vt16 + (size_t)(b * KV_ + kv) * HD_ * (CTX_ / 2);
    const int ntile = (P_ + m0 + 128) / 64;

    // tile 0 loads: 512 16B-segments per tile over 256 threads (2 each)
    {
#pragma unroll
        for (int i = 0; i < 2; i++) {
            const int sg = tid + i * 256;
            const int row = sg >> 3, off = (sg & 7) * 4;
            cp16(&KsS[0][row * 36 + off], kplane + (size_t)row * 32 + off);
            cp16(&VtS[0][row * 36 + off], vplane + (size_t)row * (CTX_ / 2) + off);
        }
        asm volatile("cp.async.commit_group;");
    }

    // Q fragments (fp16 hi/lo pairs), persist across tiles
    uint32_t qhi[4][4], qlo[4][4];
    {
        const uint2* q0 = g_Qhl + ((size_t)(b * S_ + m0 + warp * 16 + g)     * H_ + h) * 32;
        const uint2* q8 = g_Qhl + ((size_t)(b * S_ + m0 + warp * 16 + g + 8) * H_ + h) * 32;
#pragma unroll
        for (int ks = 0; ks < 4; ks++) {
            uint2 u0 = q0[tg + 8 * ks];
            uint2 u1 = q8[tg + 8 * ks];
            uint2 u2 = q0[tg + 4 + 8 * ks];
            uint2 u3 = q8[tg + 4 + 8 * ks];
            qhi[ks][0] = u0.x; qhi[ks][1] = u1.x; qhi[ks][2] = u2.x; qhi[ks][3] = u3.x;
            qlo[ks][0] = u0.y; qlo[ks][1] = u1.y; qlo[ks][2] = u2.y; qlo[ks][3] = u3.y;
        }
    }

    float o[8][4];
#pragma unroll
    for (int nt = 0; nt < 8; nt++)
#pragma unroll
        for (int r = 0; r < 4; r++) o[nt][r] = 0.f;
    float m0s = -1e30f, m1s = -1e30f, l0 = 0.f, l1 = 0.f;

    const int qpos0 = P_ + m0 + warp * 16 + g;
    const int wmax  = P_ + m0 + warp * 16 + 15;

    for (int it = 0; it < ntile; ++it) {
        const int t0 = it * 64;
        const int buf = it & 1;

        if (it + 1 < ntile) {
            const int nb = (it + 1) & 1;
#pragma unroll
            for (int i = 0; i < 2; i++) {
                const int sg = tid + i * 256;
                const int row = sg >> 3, off = (sg & 7) * 4;
                cp16(&KsS[nb][row * 36 + off],
                     kplane + (size_t)(t0 + 64 + row) * 32 + off);
                cp16(&VtS[nb][row * 36 + off],
                     vplane + (size_t)row * (CTX_ / 2) + (t0 + 64) / 2 + off);
            }
            asm volatile("cp.async.commit_group;");
            asm volatile("cp.async.wait_group 1;");
        } else {
            asm volatile("cp.async.wait_group 0;");
        }
        __syncthreads();

        if (t0 <= wmax) {
            const uint32_t* KsC = KsS[buf];
            const uint32_t* VtC = VtS[buf];

            // --- scores S = Q K^T (fp16x2): 2 mmas per (ks, nt) ---
            float s[8][4];
#pragma unroll
            for (int nt = 0; nt < 8; nt++)
#pragma unroll
                for (int r = 0; r < 4; r++) s[nt][r] = 0.f;

#pragma unroll
            for (int ks = 0; ks < 4; ks++) {
#pragma unroll
                for (int nt = 0; nt < 8; nt++) {
                    const uint32_t* kb = &KsC[(8 * nt + g) * 36 + 8 * ks + tg];
                    uint32_t b0 = kb[0];
                    uint32_t b1 = kb[4];
                    mma_f16(s[nt], qhi[ks][0], qhi[ks][1], qhi[ks][2], qhi[ks][3], b0, b1);
                    mma_f16(s[nt], qlo[ks][0], qlo[ks][1], qlo[ks][2], qlo[ks][3], b0, b1);
                }
            }

            // --- scale + causal mask ---
            const bool need_mask = (t0 + 63 > P_ + m0 + warp * 16);
            if (need_mask) {
#pragma unroll
                for (int nt = 0; nt < 8; nt++) {
                    const int col = t0 + 8 * nt + 2 * tg;
#pragma unroll
                    for (int r = 0; r < 4; r++) {
                        const int c  = col + (r & 1);
                        const int qp = (r < 2) ? qpos0 : qpos0 + 8;
                        s[nt][r] = (c > qp) ? -1e30f : s[nt][r] * 0.125f;
                    }
                }
            } else {
#pragma unroll
                for (int nt = 0; nt < 8; nt++)
#pragma unroll
                    for (int r = 0; r < 4; r++) s[nt][r] *= 0.125f;
            }

            // --- online softmax ---
            float mx0 = -1e30f, mx1 = -1e30f;
#pragma unroll
            for (int nt = 0; nt < 8; nt++) {
                mx0 = fmaxf(mx0, fmaxf(s[nt][0], s[nt][1]));
                mx1 = fmaxf(mx1, fmaxf(s[nt][2], s[nt][3]));
            }
            mx0 = fmaxf(mx0, __shfl_xor_sync(0xffffffffu, mx0, 1));
            mx0 = fmaxf(mx0, __shfl_xor_sync(0xffffffffu, mx0, 2));
            mx1 = fmaxf(mx1, __shfl_xor_sync(0xffffffffu, mx1, 1));
            mx1 = fmaxf(mx1, __shfl_xor_sync(0xffffffffu, mx1, 2));

            const float mn0 = fmaxf(m0s, mx0);
            const float mn1 = fmaxf(m1s, mx1);
            const float alpha0 = __expf(m0s - mn0);
            const float alpha1 = __expf(m1s - mn1);
            m0s = mn0; m1s = mn1;

            float sum0 = 0.f, sum1 = 0.f;
#pragma unroll
            for (int nt = 0; nt < 8; nt++) {
                s[nt][0] = __expf(s[nt][0] - mn0);
                s[nt][1] = __expf(s[nt][1] - mn0);
                s[nt][2] = __expf(s[nt][2] - mn1);
                s[nt][3] = __expf(s[nt][3] - mn1);
                sum0 += s[nt][0] + s[nt][1];
                sum1 += s[nt][2] + s[nt][3];
            }
            sum0 += __shfl_xor_sync(0xffffffffu, sum0, 1);
            sum0 += __shfl_xor_sync(0xffffffffu, sum0, 2);
            sum1 += __shfl_xor_sync(0xffffffffu, sum1, 1);
            sum1 += __shfl_xor_sync(0xffffffffu, sum1, 2);
            l0 = l0 * alpha0 + sum0;
            l1 = l1 * alpha1 + sum1;

#pragma unroll
            for (int nt = 0; nt < 8; nt++) {
                o[nt][0] *= alpha0; o[nt][1] *= alpha0;
                o[nt][2] *= alpha1; o[nt][3] *= alpha1;
            }

            // --- O += P V (single-fp16 P: 1 mma per (ks, nt)) ---
#pragma unroll
            for (int ks = 0; ks < 4; ks++) {
                uint32_t a0 = h2pack(s[2 * ks][0],     s[2 * ks][1]);
                uint32_t a1 = h2pack(s[2 * ks][2],     s[2 * ks][3]);
                uint32_t a2 = h2pack(s[2 * ks + 1][0], s[2 * ks + 1][1]);
                uint32_t a3 = h2pack(s[2 * ks + 1][2], s[2 * ks + 1][3]);
#pragma unroll
                for (int nt = 0; nt < 8; nt++) {
                    const uint32_t* vb = &VtC[(8 * nt + g) * 36 + 8 * ks + tg];
                    mma_f16(o[nt], a0, a1, a2, a3, vb[0], vb[4]);
                }
            }
        }

        __syncthreads();
    }

    // --- epilogue: write fp16 pairs for the O projection ---
    const float inv0 = 1.f / l0;
    const float inv1 = 1.f / l1;
    const size_t row0  = (size_t)(b * S_ + m0 + warp * 16 + g);
    const size_t base0 = row0 * (E_ / 2) + h * (HD_ / 2) + tg;
    const size_t base8 = base0 + 4 * E_;     // +8 rows (8 * E/2)
#pragma unroll
    for (int nt = 0; nt < 8; nt++) {
        g_Ap[base0 + 4 * nt] = split2h(o[nt][0] * inv0, o[nt][1] * inv0);
        g_Ap[base8 + 4 * nt] = split2h(o[nt][2] * inv1, o[nt][3] * inv1);
    }
}

// ---------------------------------------------------------------------------
// Launcher
// ---------------------------------------------------------------------------
extern "C" void kernel_launch(void* const* d_in, const int* in_sizes, int n_in,
                              void* d_out, int out_size)
{
    const float* x       = (const float*)d_in[0];
    const float* cosp    = (const float*)d_in[1];
    const float* sinp    = (const float*)d_in[2];
    // d_in[3] = mask (causal; computed analytically)
    const float* cache_k = (const float*)d_in[4];
    const float* cache_v = (const float*)d_in[5];
    const float* Wq      = (const float*)d_in[6];
    const float* Wk      = (const float*)d_in[7];
    const float* Wv      = (const float*)d_in[8];
    const float* Wo      = (const float*)d_in[9];
    float* out           = (float*)d_out;

    uint2* xp;
    uint32_t *wq16, *wk16, *wv16, *wo16;
    cudaGetSymbolAddress((void**)&xp,   g_Xp);
    cudaGetSymbolAddress((void**)&wq16, g_Wq16);
    cudaGetSymbolAddress((void**)&wk16, g_Wk16);
    cudaGetSymbolAddress((void**)&wv16, g_Wv16);
    cudaGetSymbolAddress((void**)&wo16, g_Wo16);

    cudaFuncSetAttribute(gemm_qkv, cudaFuncAttributeMaxDynamicSharedMemorySize, GSM2);
    cudaFuncSetAttribute(gemm_o,   cudaFuncAttributeMaxDynamicSharedMemorySize, GSM2);

    // 0) fp16 planes: x -> (hi,lo) pairs; weights -> single fp16
    split_pairs<<<(M_ * E_ / 2 + 255) / 256, 256>>>(x, xp, M_ * E_ / 2);
    tohalf_pairs<<<(E_ * E_ / 2 + 255) / 256, 256>>>(Wq, wq16, E_ * E_ / 2);
    tohalf_pairs<<<(KV_ * HD_ * E_ / 2 + 255) / 256, 256>>>(Wk, wk16, KV_ * HD_ * E_ / 2);
    tohalf_pairs<<<(KV_ * HD_ * E_ / 2 + 255) / 256, 256>>>(Wv, wv16, KV_ * HD_ * E_ / 2);
    tohalf_pairs<<<(E_ * E_ / 2 + 255) / 256, 256>>>(Wo, wo16, E_ * E_ / 2);

    // 1) fused Q/K/V projections (fp16x2 tensor cores)
    gemm_qkv<<<dim3(24, M_ / 128), 256, GSM2>>>();

    // 2) RoPE + fp16 split of Q and new K
    {
        const int total = M_ * (H_ + KV_) * 16;
        rope_split_kernel<<<(total + 255) / 256, 256>>>(cosp, sinp);
    }

    // 3) cached K + all V into fp16 planes (V transposed)
    prep_kv<<<dim3(CTX_ / 64, KV_, B_), 256>>>(cache_k, cache_v);

    // 4) flash attention (fp16x2 QK, fp16 PV, BLOCK_M=128)
    attn_mma<<<dim3(S_ / 128, H_, B_), 256>>>();

    // 5) output projection (fp16x2)
    gemm_o<<<dim3(16, 16), 256, GSM2>>>(out);
}